// round 1
// baseline (speedup 1.0000x reference)
#include <cuda_runtime.h>
#include <math.h>

// Problem dims
#define Tt 16
#define Mm 1024
#define Hh 128
#define NHEADS 4
#define ROWS (Tt * Mm)   // 16384 (= M*T for the transformer too)
#define MAXD 128
#define NL_TR 5

// ---------------- scratch (device globals; no allocations) ----------------
__device__ float g_h[ROWS * 512];          // GAT head projections [row][head*128+d]
__device__ float g_xa[ROWS * Hh];          // GAT ping
__device__ float g_xb[ROWS * Hh];          // GAT pong
__device__ float g_ss[ROWS * NHEADS];      // source scores
__device__ float g_sd[ROWS * NHEADS];      // dest scores
__device__ unsigned char g_m[ROWS];        // node mask per (t, node)
__device__ int g_cnt[ROWS];                // neighbor counts
__device__ unsigned short g_nbr[ROWS * MAXD];
__device__ float g_xs[ROWS * Hh];          // x_seq [m][t][d]
__device__ float g_q[ROWS * Hh];
__device__ float g_k[ROWS * Hh];
__device__ float g_v[ROWS * Hh];
__device__ float g_att[ROWS * Hh];
__device__ float g_r[ROWS * Hh];
__device__ float g_ff[ROWS * 512];

// ---------------- mask + self-loop init ----------------
__global__ void mask_init(const unsigned char* __restrict__ ego) {
    int idx = blockIdx.x * 256 + threadIdx.x;
    if (idx >= ROWS) return;
    int t = idx >> 10;
    int mm = idx & 1023;
    int b = mm >> 8;
    int n = mm & 255;
    // ego_mask[b, t, n] -> m[t, b*N+n]
    unsigned char v = ego[(b * Tt + t) * 256 + n] ? 1 : 0;
    g_m[idx] = v;
    g_cnt[idx] = v ? 1 : 0;                 // self-loop preinstalled
    g_nbr[idx * MAXD] = (unsigned short)mm;
}

// ---------------- neighbor-list build (edge j->i iff A[t,j,i]!=0 & masks) ----------------
__global__ void build_nbr(const float* __restrict__ A) {
    int tj = blockIdx.x >> 2;                       // t*1024 + j
    int i = ((blockIdx.x & 3) << 8) + threadIdx.x;  // dest node
    if (!g_m[tj]) return;                           // source must be masked in
    int t = tj >> 10;
    int j = tj & 1023;
    if (i == j) return;                             // self-loop handled in init
    float a = A[(size_t)tj * 1024 + i];
    int ti = (t << 10) + i;
    if (a != 0.f && g_m[ti]) {
        int pos = atomicAdd(&g_cnt[ti], 1);
        if (pos < MAXD) g_nbr[ti * MAXD + pos] = (unsigned short)j;
    }
}

// ---------------- GAT layer-0 projection (FIN=2) ----------------
__global__ void gat_proj0(const float* __restrict__ x, const float* __restrict__ W) {
    int idx = blockIdx.x * 256 + threadIdx.x;   // ROWS*512
    int row = idx >> 9;
    int c = idx & 511;
    g_h[idx] = x[row * 2] * W[c] + x[row * 2 + 1] * W[512 + c];
}

// ---------------- per-(row, head) src/dst attention scores ----------------
__global__ void ssd_kernel(const float* __restrict__ asrc, const float* __restrict__ adst) {
    int row = blockIdx.x;
    int w = threadIdx.x >> 5;       // head
    int lane = threadIdx.x & 31;
    const float* hp = g_h + (size_t)row * 512 + w * 128;
    const float* as = asrc + w * 128;
    const float* ad = adst + w * 128;
    float s1 = 0.f, s2 = 0.f;
#pragma unroll
    for (int d = lane; d < 128; d += 32) {
        float hv = hp[d];
        s1 += hv * as[d];
        s2 += hv * ad[d];
    }
#pragma unroll
    for (int o = 16; o; o >>= 1) {
        s1 += __shfl_down_sync(0xFFFFFFFFu, s1, o);
        s2 += __shfl_down_sync(0xFFFFFFFFu, s2, o);
    }
    if (lane == 0) {
        g_ss[row * 4 + w] = s1;
        g_sd[row * 4 + w] = s2;
    }
}

// ---------------- sparse segment-softmax + aggregation + head mean + bias + relu ----------------
__global__ void gat_agg(const float* __restrict__ bias, float* __restrict__ xout) {
    int row = blockIdx.x;       // t*1024 + i
    int tid = threadIdx.x;      // 128
    if (!g_m[row]) { xout[(size_t)row * 128 + tid] = 0.f; return; }
    int t = row >> 10;

    __shared__ unsigned short nb[MAXD];
    __shared__ float w[4][MAXD];

    int cnt = g_cnt[row];
    if (cnt > MAXD) cnt = MAXD;
    if (tid < cnt) nb[tid] = g_nbr[(size_t)row * MAXD + tid];

    // logits per (neighbor slot, head)
    if (tid < cnt) {
        int jr = (t << 10) + nb[tid];
#pragma unroll
        for (int hh = 0; hh < 4; hh++) {
            float z = g_sd[row * 4 + hh] + g_ss[jr * 4 + hh];
            w[hh][tid] = (z > 0.f) ? z : 0.2f * z;      // leaky_relu 0.2
        }
    } else {
#pragma unroll
        for (int hh = 0; hh < 4; hh++) w[hh][tid] = -INFINITY;
    }
    __syncthreads();

    // per-head softmax over neighbor slots (warp wh handles head wh)
    {
        int wh = tid >> 5, lane = tid & 31;
        float v0 = w[wh][lane], v1 = w[wh][lane + 32], v2 = w[wh][lane + 64], v3 = w[wh][lane + 96];
        float mx = fmaxf(fmaxf(v0, v1), fmaxf(v2, v3));
#pragma unroll
        for (int o = 16; o; o >>= 1) mx = fmaxf(mx, __shfl_xor_sync(0xFFFFFFFFu, mx, o));
        float e0 = expf(v0 - mx), e1 = expf(v1 - mx), e2 = expf(v2 - mx), e3 = expf(v3 - mx);
        float s = e0 + e1 + e2 + e3;
#pragma unroll
        for (int o = 16; o; o >>= 1) s += __shfl_xor_sync(0xFFFFFFFFu, s, o);
        float inv = 1.f / s;
        w[wh][lane] = e0 * inv;
        w[wh][lane + 32] = e1 * inv;
        w[wh][lane + 64] = e2 * inv;
        w[wh][lane + 96] = e3 * inv;
    }
    __syncthreads();

    // aggregate: thread = output dim d
    float acc = 0.f;
#pragma unroll
    for (int hh = 0; hh < 4; hh++) {
        const float* hb = g_h + ((size_t)(t << 10) << 9) + (hh << 7) + tid;
        for (int j = 0; j < cnt; j++) {
            acc += w[hh][j] * hb[(size_t)nb[j] << 9];
        }
    }
    float o = acc * 0.25f + bias[tid];
    xout[(size_t)row * 128 + tid] = fmaxf(o, 0.f);
}

// ---------------- transpose to sequence layout + sinusoidal PE ----------------
__global__ void to_seq(const float* __restrict__ xin) {
    int idx = blockIdx.x * 256 + threadIdx.x;   // ROWS*128
    int row = idx >> 7;     // t*1024 + m
    int d = idx & 127;
    int t = row >> 10;
    int mm = row & 1023;
    float freq = expf(-(float)(d & ~1) * (9.210340371976184f / 128.f));
    float ang = (float)t * freq;
    float pe = (d & 1) ? cosf(ang) : sinf(ang);
    g_xs[((size_t)mm * Tt + t) * Hh + d] = xin[idx] + pe;
}

// ---------------- SGEMM: 128x128 tile, BK=8, 8x8 per thread ----------------
// C[row,col] = act( A@B + bias (+ residual) ); rows%128==0, N%128==0, K%8==0
template <int ACT, bool RESID>
__global__ void __launch_bounds__(256, 2)
sgemm(const float* __restrict__ A, const float* __restrict__ B,
      const float* __restrict__ bias, const float* __restrict__ R,
      float* __restrict__ C, int N_, int K_) {
    __shared__ float As[8][128];
    __shared__ float Bs[8][128];
    const int tid = threadIdx.x;
    const int tx = tid & 15, ty = tid >> 4;
    const int bx = blockIdx.x, by = blockIdx.y;

    float acc[8][8];
#pragma unroll
    for (int i = 0; i < 8; i++)
#pragma unroll
        for (int j = 0; j < 8; j++) acc[i][j] = 0.f;

    const int a_row = tid >> 1, a_kc = (tid & 1) * 4;
    const int b_kr = tid >> 5, b_c = (tid & 31) * 4;
    const float* Ap = A + (size_t)(by * 128 + a_row) * K_ + a_kc;
    const float* Bp = B + (size_t)b_kr * N_ + bx * 128 + b_c;

    for (int k0 = 0; k0 < K_; k0 += 8) {
        float4 av = *(const float4*)Ap;  Ap += 8;
        float4 bv = *(const float4*)Bp;  Bp += (size_t)8 * N_;
        As[a_kc + 0][a_row] = av.x;
        As[a_kc + 1][a_row] = av.y;
        As[a_kc + 2][a_row] = av.z;
        As[a_kc + 3][a_row] = av.w;
        *(float4*)&Bs[b_kr][b_c] = bv;
        __syncthreads();
#pragma unroll
        for (int kk = 0; kk < 8; kk++) {
            float4 a0 = ((const float4*)As[kk])[ty];
            float4 a1 = ((const float4*)As[kk])[16 + ty];
            float4 b0 = ((const float4*)Bs[kk])[tx];
            float4 b1 = ((const float4*)Bs[kk])[16 + tx];
            float af[8] = {a0.x, a0.y, a0.z, a0.w, a1.x, a1.y, a1.z, a1.w};
            float bf[8] = {b0.x, b0.y, b0.z, b0.w, b1.x, b1.y, b1.z, b1.w};
#pragma unroll
            for (int i = 0; i < 8; i++)
#pragma unroll
                for (int j = 0; j < 8; j++) acc[i][j] += af[i] * bf[j];
        }
        __syncthreads();
    }

#pragma unroll
    for (int ih = 0; ih < 2; ih++)
#pragma unroll
        for (int ii = 0; ii < 4; ii++) {
            int row = by * 128 + ih * 64 + ty * 4 + ii;
#pragma unroll
            for (int jh = 0; jh < 2; jh++)
#pragma unroll
                for (int jj = 0; jj < 4; jj++) {
                    int col = bx * 128 + jh * 64 + tx * 4 + jj;
                    float v = acc[ih * 4 + ii][jh * 4 + jj];
                    if (bias) v += bias[col];
                    if (RESID) v += R[(size_t)row * N_ + col];
                    if (ACT == 1) v = fmaxf(v, 0.f);
                    C[(size_t)row * N_ + col] = v;
                }
        }
}

// ---------------- per-sequence attention (T=16, 4 heads of 32) ----------------
__global__ void attn_kernel(const float* __restrict__ Q, const float* __restrict__ K,
                            const float* __restrict__ V, float* __restrict__ O) {
    __shared__ float sq[16][128], sk[16][128], sv[16][128];
    int m = blockIdx.x;
    int tid = threadIdx.x;   // 128
    size_t base = (size_t)m * 16 * 128;
    for (int idx = tid; idx < 2048; idx += 128) {
        sq[idx >> 7][idx & 127] = Q[base + idx];
        sk[idx >> 7][idx & 127] = K[base + idx];
        sv[idx >> 7][idx & 127] = V[base + idx];
    }
    __syncthreads();
    if (tid < 64) {
        int h = tid >> 4, tq = tid & 15;
        const float scale = 0.17677669529663687f;  // 1/sqrt(32)
        float sc[16];
        float mx = -1e30f;
#pragma unroll
        for (int tk = 0; tk < 16; tk++) {
            float s = 0.f;
#pragma unroll
            for (int d = 0; d < 32; d++) s += sq[tq][h * 32 + d] * sk[tk][h * 32 + d];
            s *= scale;
            sc[tk] = s;
            mx = fmaxf(mx, s);
        }
        float sum = 0.f;
#pragma unroll
        for (int tk = 0; tk < 16; tk++) { sc[tk] = expf(sc[tk] - mx); sum += sc[tk]; }
        float inv = 1.f / sum;
#pragma unroll
        for (int d = 0; d < 32; d++) {
            float o = 0.f;
#pragma unroll
            for (int tk = 0; tk < 16; tk++) o += sc[tk] * sv[tk][h * 32 + d];
            O[base + (size_t)tq * 128 + h * 32 + d] = o * inv;
        }
    }
}

// ---------------- LayerNorm over last dim (128) ----------------
__global__ void ln_kernel(const float* __restrict__ in, const float* __restrict__ s,
                          const float* __restrict__ b, float* __restrict__ out) {
    int row = blockIdx.x;
    int tid = threadIdx.x;   // 128
    __shared__ float red[8];
    float x = in[(size_t)row * 128 + tid];
    float sum = x;
#pragma unroll
    for (int o = 16; o; o >>= 1) sum += __shfl_xor_sync(0xFFFFFFFFu, sum, o);
    if ((tid & 31) == 0) red[tid >> 5] = sum;
    __syncthreads();
    float mean = (red[0] + red[1] + red[2] + red[3]) * (1.f / 128.f);
    float dd = x - mean;
    float qq = dd * dd;
#pragma unroll
    for (int o = 16; o; o >>= 1) qq += __shfl_xor_sync(0xFFFFFFFFu, qq, o);
    if ((tid & 31) == 0) red[4 + (tid >> 5)] = qq;
    __syncthreads();
    float var = (red[4] + red[5] + red[6] + red[7]) * (1.f / 128.f);
    out[(size_t)row * 128 + tid] = dd * rsqrtf(var + 1e-5f) * s[tid] + b[tid];
}

// ---------------- launcher ----------------
extern "C" void kernel_launch(void* const* d_in, const int* in_sizes, int n_in,
                              void* d_out, int out_size) {
    const unsigned char* ego = (const unsigned char*)d_in[0];
    const float* positions  = (const float*)d_in[1];
    const float* adjacency  = (const float*)d_in[2];
    const float* gat1_W     = (const float*)d_in[3];
    const float* gat1_asrc  = (const float*)d_in[4];
    const float* gat1_adst  = (const float*)d_in[5];
    const float* gat1_b     = (const float*)d_in[6];
    const float* gatW       = (const float*)d_in[7];
    const float* gat_asrc   = (const float*)d_in[8];
    const float* gat_adst   = (const float*)d_in[9];
    const float* gat_b      = (const float*)d_in[10];
    const float* Wqkv       = (const float*)d_in[11];
    const float* bqkv       = (const float*)d_in[12];
    const float* Wo         = (const float*)d_in[13];
    const float* bo         = (const float*)d_in[14];
    const float* ln1_s      = (const float*)d_in[15];
    const float* ln1_b      = (const float*)d_in[16];
    const float* ln2_s      = (const float*)d_in[17];
    const float* ln2_b      = (const float*)d_in[18];
    const float* Wff1       = (const float*)d_in[19];
    const float* bff1       = (const float*)d_in[20];
    const float* Wff2       = (const float*)d_in[21];
    const float* bff2       = (const float*)d_in[22];
    float* out = (float*)d_out;

    float *h, *xa, *xb, *xs, *q, *k, *v, *att, *r, *ff;
    cudaGetSymbolAddress((void**)&h,   g_h);
    cudaGetSymbolAddress((void**)&xa,  g_xa);
    cudaGetSymbolAddress((void**)&xb,  g_xb);
    cudaGetSymbolAddress((void**)&xs,  g_xs);
    cudaGetSymbolAddress((void**)&q,   g_q);
    cudaGetSymbolAddress((void**)&k,   g_k);
    cudaGetSymbolAddress((void**)&v,   g_v);
    cudaGetSymbolAddress((void**)&att, g_att);
    cudaGetSymbolAddress((void**)&r,   g_r);
    cudaGetSymbolAddress((void**)&ff,  g_ff);

    // Edge structure (constant across GAT layers)
    mask_init<<<ROWS / 256, 256>>>(ego);
    build_nbr<<<ROWS * 4, 256>>>(adjacency);

    // GAT layer 0 (FIN=2)
    gat_proj0<<<ROWS * 512 / 256, 256>>>(positions, gat1_W);
    ssd_kernel<<<ROWS, 128>>>(gat1_asrc, gat1_adst);
    gat_agg<<<ROWS, 128>>>(gat1_b, xa);

    // GAT layers 1..5 (FIN=128)
    float* cur = xa;
    float* nxt = xb;
    for (int i = 0; i < 5; i++) {
        dim3 gp(512 / 128, ROWS / 128);
        sgemm<0, false><<<gp, 256>>>(cur, gatW + (size_t)i * 128 * 512, nullptr, nullptr, h, 512, 128);
        ssd_kernel<<<ROWS, 128>>>(gat_asrc + i * 512, gat_adst + i * 512);
        gat_agg<<<ROWS, 128>>>(gat_b + i * 128, nxt);
        float* tmp = cur; cur = nxt; nxt = tmp;
    }

    // Sequence layout + positional encoding
    to_seq<<<ROWS * 128 / 256, 256>>>(cur);

    // Transformer layers
    dim3 g1(1, ROWS / 128);
    dim3 g2(4, ROWS / 128);
    for (int l = 0; l < NL_TR; l++) {
        const float* Wq = Wqkv + (size_t)(l * 3 + 0) * 128 * 128;
        const float* Wk = Wqkv + (size_t)(l * 3 + 1) * 128 * 128;
        const float* Wv = Wqkv + (size_t)(l * 3 + 2) * 128 * 128;
        sgemm<0, false><<<g1, 256>>>(xs, Wq, bqkv + (l * 3 + 0) * 128, nullptr, q, 128, 128);
        sgemm<0, false><<<g1, 256>>>(xs, Wk, bqkv + (l * 3 + 1) * 128, nullptr, k, 128, 128);
        sgemm<0, false><<<g1, 256>>>(xs, Wv, bqkv + (l * 3 + 2) * 128, nullptr, v, 128, 128);
        attn_kernel<<<Mm, 128>>>(q, k, v, att);
        sgemm<0, true><<<g1, 256>>>(att, Wo + (size_t)l * 128 * 128, bo + l * 128, xs, r, 128, 128);
        ln_kernel<<<ROWS, 128>>>(r, ln1_s + l * 128, ln1_b + l * 128, xs);
        sgemm<1, false><<<g2, 256>>>(xs, Wff1 + (size_t)l * 128 * 512, bff1 + l * 512, nullptr, ff, 512, 128);
        sgemm<0, true><<<g1, 256>>>(ff, Wff2 + (size_t)l * 512 * 128, bff2 + l * 128, xs, r, 128, 512);
        float* lnout = (l == NL_TR - 1) ? out : xs;
        ln_kernel<<<ROWS, 128>>>(r, ln2_s + l * 128, ln2_b + l * 128, lnout);
    }
}

// round 3
// speedup vs baseline: 1.0722x; 1.0722x over previous
#include <cuda_runtime.h>
#include <cuda_bf16.h>
#include <math.h>

// Problem dims
#define Tt 16
#define Mm 1024
#define Hh 128
#define NHEADS 4
#define ROWS (Tt * Mm)   // 16384
#define MAXD 128
#define NL_TR 5

// ---------------- scratch (device globals; no allocations) ----------------
__device__ float g_h[ROWS * 512];
__device__ float g_xa[ROWS * Hh];
__device__ float g_xb[ROWS * Hh];
__device__ float g_ss[ROWS * NHEADS];
__device__ float g_sd[ROWS * NHEADS];
__device__ unsigned char g_m[ROWS];
__device__ int g_cnt[ROWS];
__device__ unsigned short g_nbr[ROWS * MAXD];
__device__ float g_xs[ROWS * Hh];
__device__ float g_q[ROWS * Hh];
__device__ float g_k[ROWS * Hh];
__device__ float g_v[ROWS * Hh];
__device__ float g_att[ROWS * Hh];
__device__ float g_r[ROWS * Hh];
__device__ float g_ff[ROWS * 512];

// Pre-split weights (bf16 hi/lo, transposed to [N, K])
#define WTOT 1310720
#define OFF_GAT 0
#define OFF_QKV 327680
#define OFF_WO  573440
#define OFF_FF1 655360
#define OFF_FF2 983040
__device__ __nv_bfloat16 g_wh[WTOT];
__device__ __nv_bfloat16 g_wl[WTOT];

__device__ __forceinline__ unsigned smem_u32(const void* p) {
    unsigned a;
    asm("{ .reg .u64 t; cvta.to.shared.u64 t, %1; cvt.u32.u64 %0, t; }" : "=r"(a) : "l"(p));
    return a;
}
__device__ __forceinline__ void ldmat4(unsigned& r0, unsigned& r1, unsigned& r2, unsigned& r3, unsigned addr) {
    asm volatile("ldmatrix.sync.aligned.m8n8.x4.shared.b16 {%0,%1,%2,%3}, [%4];"
        : "=r"(r0), "=r"(r1), "=r"(r2), "=r"(r3) : "r"(addr));
}
__device__ __forceinline__ void mma16816(float* c, unsigned a0, unsigned a1, unsigned a2, unsigned a3,
                                         unsigned b0, unsigned b1) {
    asm volatile("mma.sync.aligned.m16n8k16.row.col.f32.bf16.bf16.f32 "
        "{%0,%1,%2,%3}, {%4,%5,%6,%7}, {%8,%9}, {%0,%1,%2,%3};"
        : "+f"(c[0]), "+f"(c[1]), "+f"(c[2]), "+f"(c[3])
        : "r"(a0), "r"(a1), "r"(a2), "r"(a3), "r"(b0), "r"(b1));
}

// SMEM layout: 4 tile buffers (A hi/lo, B hi/lo), 128 rows x 72 bf16 (144B stride)
#define TROW 144
#define TBUF (128 * TROW)     // 18432 B
#define SM_AHI 0
#define SM_ALO TBUF
#define SM_BHI (2 * TBUF)
#define SM_BLO (3 * TBUF)
#define GSM_TOTAL (4 * TBUF)  // 73728 B (stage 128*132*4=67584 fits inside)

// ---------------- HMMA GEMM: C[128x128 tile] = act(A @ B^T + bias (+R)) ----------------
// A fp32 [rows, K]; B pre-split bf16 hi/lo [Ntot, K]; 3xBF16 split accumulation.
template <int ACT, bool RESID, bool SCORES>
__global__ void __launch_bounds__(256)
gemm_tc(const float* __restrict__ A, const __nv_bfloat16* __restrict__ Bh,
        const __nv_bfloat16* __restrict__ Bl, const float* __restrict__ bias,
        const float* __restrict__ Rr, float* __restrict__ C,
        const float* __restrict__ asrc, const float* __restrict__ adst,
        float* __restrict__ gss, float* __restrict__ gsd, int Nt, int Kt) {
    extern __shared__ char smem[];
    const unsigned sb = smem_u32(smem);
    const int tid = threadIdx.x;
    const int wid = tid >> 5, lane = tid & 31;
    const int wr = wid >> 1, wc = wid & 1;     // warp tile: rows wr*32, cols wc*64
    const int row0 = blockIdx.y * 128;
    const int col0 = blockIdx.x * 128;

    float acc[2][8][4];
#pragma unroll
    for (int mt = 0; mt < 2; mt++)
#pragma unroll
        for (int nt = 0; nt < 8; nt++)
#pragma unroll
            for (int e = 0; e < 4; e++) acc[mt][nt][e] = 0.f;

    const int ltile = lane >> 3, lrow = lane & 7;

    for (int kc = 0; kc < Kt; kc += 64) {
        // stage A chunk: 128 rows x 64 k fp32 -> bf16 hi/lo
        for (int i = tid; i < 128 * 16; i += 256) {
            int r = i >> 4, q = i & 15;
            float4 v = *(const float4*)(A + (size_t)(row0 + r) * Kt + kc + q * 4);
            __nv_bfloat16 h0 = __float2bfloat16(v.x), h1 = __float2bfloat16(v.y);
            __nv_bfloat16 h2 = __float2bfloat16(v.z), h3 = __float2bfloat16(v.w);
            __nv_bfloat16 l0 = __float2bfloat16(v.x - __bfloat162float(h0));
            __nv_bfloat16 l1 = __float2bfloat16(v.y - __bfloat162float(h1));
            __nv_bfloat16 l2 = __float2bfloat16(v.z - __bfloat162float(h2));
            __nv_bfloat16 l3 = __float2bfloat16(v.w - __bfloat162float(h3));
            uint2 uh, ul;
            uh.x = (unsigned)__bfloat16_as_ushort(h0) | ((unsigned)__bfloat16_as_ushort(h1) << 16);
            uh.y = (unsigned)__bfloat16_as_ushort(h2) | ((unsigned)__bfloat16_as_ushort(h3) << 16);
            ul.x = (unsigned)__bfloat16_as_ushort(l0) | ((unsigned)__bfloat16_as_ushort(l1) << 16);
            ul.y = (unsigned)__bfloat16_as_ushort(l2) | ((unsigned)__bfloat16_as_ushort(l3) << 16);
            int off = r * TROW + q * 8;
            *(uint2*)(smem + SM_AHI + off) = uh;
            *(uint2*)(smem + SM_ALO + off) = ul;
        }
        // stage B chunk: 128 n x 64 k bf16 hi/lo
        for (int i = tid; i < 128 * 8; i += 256) {
            int n = i >> 3, q = i & 7;
            size_t ga = (size_t)(col0 + n) * Kt + kc + q * 8;
            uint4 vh = *(const uint4*)(Bh + ga);
            uint4 vl = *(const uint4*)(Bl + ga);
            int off = n * TROW + q * 16;
            *(uint4*)(smem + SM_BHI + off) = vh;
            *(uint4*)(smem + SM_BLO + off) = vl;
        }
        __syncthreads();

#pragma unroll
        for (int ks = 0; ks < 4; ks++) {
            // A fragments (both m-tiles, hi & lo)
            unsigned ah[2][4], al[2][4];
#pragma unroll
            for (int mt = 0; mt < 2; mt++) {
                int row = wr * 32 + mt * 16 + lrow + (ltile & 1) * 8;
                int kcol = ks * 16 + (ltile >> 1) * 8;
                unsigned off = (unsigned)(row * TROW + kcol * 2);
                ldmat4(ah[mt][0], ah[mt][1], ah[mt][2], ah[mt][3], sb + SM_AHI + off);
                ldmat4(al[mt][0], al[mt][1], al[mt][2], al[mt][3], sb + SM_ALO + off);
            }
            // B fragments per 16-col group, mma immediately
#pragma unroll
            for (int g = 0; g < 4; g++) {
                int n = wc * 64 + g * 16 + lrow + (ltile >> 1) * 8;
                int kcol = ks * 16 + (ltile & 1) * 8;
                unsigned off = (unsigned)(n * TROW + kcol * 2);
                unsigned bh[4], bl[4];
                ldmat4(bh[0], bh[1], bh[2], bh[3], sb + SM_BHI + off);
                ldmat4(bl[0], bl[1], bl[2], bl[3], sb + SM_BLO + off);
#pragma unroll
                for (int mt = 0; mt < 2; mt++)
#pragma unroll
                    for (int half = 0; half < 2; half++) {
                        float* cc = acc[mt][g * 2 + half];
                        mma16816(cc, ah[mt][0], ah[mt][1], ah[mt][2], ah[mt][3],
                                 bh[half * 2], bh[half * 2 + 1]);
                        mma16816(cc, ah[mt][0], ah[mt][1], ah[mt][2], ah[mt][3],
                                 bl[half * 2], bl[half * 2 + 1]);
                        mma16816(cc, al[mt][0], al[mt][1], al[mt][2], al[mt][3],
                                 bh[half * 2], bh[half * 2 + 1]);
                    }
            }
        }
        __syncthreads();
    }

    // stage accumulators to smem (stride 132 floats) for coalesced epilogue
    float* stage = (float*)smem;
#pragma unroll
    for (int mt = 0; mt < 2; mt++)
#pragma unroll
        for (int nt = 0; nt < 8; nt++) {
            int row = wr * 32 + mt * 16 + (lane >> 2);
            int col = wc * 64 + nt * 8 + (lane & 3) * 2;
            float2 v0 = make_float2(acc[mt][nt][0], acc[mt][nt][1]);
            float2 v1 = make_float2(acc[mt][nt][2], acc[mt][nt][3]);
            *(float2*)(stage + (size_t)row * 132 + col) = v0;
            *(float2*)(stage + (size_t)(row + 8) * 132 + col) = v1;
        }
    __syncthreads();

    // coalesced epilogue
    for (int i = tid; i < 128 * 32; i += 256) {
        int r = i >> 5, q = i & 31;
        int c = q * 4;
        float4 v = *(float4*)(stage + (size_t)r * 132 + c);
        if (bias) {
            v.x += bias[col0 + c];
            v.y += bias[col0 + c + 1];
            v.z += bias[col0 + c + 2];
            v.w += bias[col0 + c + 3];
        }
        if (RESID) {
            float4 rr = *(const float4*)(Rr + (size_t)(row0 + r) * Nt + col0 + c);
            v.x += rr.x; v.y += rr.y; v.z += rr.z; v.w += rr.w;
        }
        if (ACT == 1) {
            v.x = fmaxf(v.x, 0.f); v.y = fmaxf(v.y, 0.f);
            v.z = fmaxf(v.z, 0.f); v.w = fmaxf(v.w, 0.f);
        }
        *(float4*)(C + (size_t)(row0 + r) * Nt + col0 + c) = v;
    }

    // fused GAT src/dst scores (col0 selects head, blockIdx.x = head)
    if (SCORES && tid < 128) {
        int r = tid;
        float s1 = 0.f, s2 = 0.f;
        const float* as = asrc + col0;
        const float* ad = adst + col0;
        const float* sp = stage + (size_t)r * 132;
#pragma unroll 8
        for (int c = 0; c < 128; c++) {
            float hv = sp[c];
            s1 += hv * as[c];
            s2 += hv * ad[c];
        }
        gss[(size_t)(row0 + r) * 4 + blockIdx.x] = s1;
        gsd[(size_t)(row0 + r) * 4 + blockIdx.x] = s2;
    }
}

// ---------------- weight pre-split + transpose to [N, K] bf16 hi/lo ----------------
__global__ void split_weights(const float* __restrict__ gatW, const float* __restrict__ Wqkv,
                              const float* __restrict__ Wo, const float* __restrict__ Wff1,
                              const float* __restrict__ Wff2) {
    int idx = blockIdx.x * 256 + threadIdx.x;
    if (idx >= WTOT) return;
    float v;
    if (idx < OFF_QKV) {                    // gatW [128,512] -> [512,128]
        int i = idx >> 16, r = idx & 65535;
        int n = r >> 7, k = r & 127;
        v = gatW[(i << 16) + k * 512 + n];
    } else if (idx < OFF_WO) {              // Wqkv [128,128]^T
        int r0 = idx - OFF_QKV;
        int i = r0 >> 14, r = r0 & 16383;
        int n = r >> 7, k = r & 127;
        v = Wqkv[(i << 14) + k * 128 + n];
    } else if (idx < OFF_FF1) {             // Wo
        int r0 = idx - OFF_WO;
        int i = r0 >> 14, r = r0 & 16383;
        int n = r >> 7, k = r & 127;
        v = Wo[(i << 14) + k * 128 + n];
    } else if (idx < OFF_FF2) {             // Wff1 [128,512] -> [512,128]
        int r0 = idx - OFF_FF1;
        int i = r0 >> 16, r = r0 & 65535;
        int n = r >> 7, k = r & 127;
        v = Wff1[(i << 16) + k * 512 + n];
    } else {                                // Wff2 [512,128] -> [128,512]
        int r0 = idx - OFF_FF2;
        int i = r0 >> 16, r = r0 & 65535;
        int n = r >> 9, k = r & 511;
        v = Wff2[(i << 16) + k * 128 + n];
    }
    __nv_bfloat16 h = __float2bfloat16(v);
    g_wh[idx] = h;
    g_wl[idx] = __float2bfloat16(v - __bfloat162float(h));
}

// ---------------- mask + self-loop init ----------------
__global__ void mask_init(const unsigned char* __restrict__ ego) {
    int idx = blockIdx.x * 256 + threadIdx.x;
    if (idx >= ROWS) return;
    int t = idx >> 10;
    int mm = idx & 1023;
    int b = mm >> 8;
    int n = mm & 255;
    unsigned char v = ego[(b * Tt + t) * 256 + n] ? 1 : 0;
    g_m[idx] = v;
    g_cnt[idx] = v ? 1 : 0;
    g_nbr[idx * MAXD] = (unsigned short)mm;
}

// ---------------- neighbor-list build ----------------
__global__ void build_nbr(const float* __restrict__ A) {
    int tj = blockIdx.x >> 2;
    int i = ((blockIdx.x & 3) << 8) + threadIdx.x;
    if (!g_m[tj]) return;
    int t = tj >> 10;
    int j = tj & 1023;
    if (i == j) return;
    float a = A[(size_t)tj * 1024 + i];
    int ti = (t << 10) + i;
    if (a != 0.f && g_m[ti]) {
        int pos = atomicAdd(&g_cnt[ti], 1);
        if (pos < MAXD) g_nbr[ti * MAXD + pos] = (unsigned short)j;
    }
}

// ---------------- GAT layer-0 projection (FIN=2) ----------------
__global__ void gat_proj0(const float* __restrict__ x, const float* __restrict__ W) {
    int idx = blockIdx.x * 256 + threadIdx.x;
    int row = idx >> 9;
    int c = idx & 511;
    g_h[idx] = x[row * 2] * W[c] + x[row * 2 + 1] * W[512 + c];
}

// ---------------- per-(row, head) scores for layer 0 ----------------
__global__ void ssd_kernel(const float* __restrict__ asrc, const float* __restrict__ adst) {
    int row = blockIdx.x;
    int w = threadIdx.x >> 5;
    int lane = threadIdx.x & 31;
    const float* hp = g_h + (size_t)row * 512 + w * 128;
    const float* as = asrc + w * 128;
    const float* ad = adst + w * 128;
    float s1 = 0.f, s2 = 0.f;
#pragma unroll
    for (int d = lane; d < 128; d += 32) {
        float hv = hp[d];
        s1 += hv * as[d];
        s2 += hv * ad[d];
    }
#pragma unroll
    for (int o = 16; o; o >>= 1) {
        s1 += __shfl_down_sync(0xFFFFFFFFu, s1, o);
        s2 += __shfl_down_sync(0xFFFFFFFFu, s2, o);
    }
    if (lane == 0) {
        g_ss[row * 4 + w] = s1;
        g_sd[row * 4 + w] = s2;
    }
}

// ---------------- sparse segment-softmax + aggregation ----------------
__global__ void gat_agg(const float* __restrict__ bias, float* __restrict__ xout) {
    int row = blockIdx.x;
    int tid = threadIdx.x;
    if (!g_m[row]) { xout[(size_t)row * 128 + tid] = 0.f; return; }
    int t = row >> 10;

    __shared__ unsigned short nb[MAXD];
    __shared__ float w[4][MAXD];

    int cnt = g_cnt[row];
    if (cnt > MAXD) cnt = MAXD;
    if (tid < cnt) nb[tid] = g_nbr[(size_t)row * MAXD + tid];

    if (tid < cnt) {
        int jr = (t << 10) + nb[tid];
#pragma unroll
        for (int hh = 0; hh < 4; hh++) {
            float z = g_sd[row * 4 + hh] + g_ss[jr * 4 + hh];
            w[hh][tid] = (z > 0.f) ? z : 0.2f * z;
        }
    } else {
#pragma unroll
        for (int hh = 0; hh < 4; hh++) w[hh][tid] = -INFINITY;
    }
    __syncthreads();

    {
        int wh = tid >> 5, lane = tid & 31;
        float v0 = w[wh][lane], v1 = w[wh][lane + 32], v2 = w[wh][lane + 64], v3 = w[wh][lane + 96];
        float mx = fmaxf(fmaxf(v0, v1), fmaxf(v2, v3));
#pragma unroll
        for (int o = 16; o; o >>= 1) mx = fmaxf(mx, __shfl_xor_sync(0xFFFFFFFFu, mx, o));
        float e0 = expf(v0 - mx), e1 = expf(v1 - mx), e2 = expf(v2 - mx), e3 = expf(v3 - mx);
        float s = e0 + e1 + e2 + e3;
#pragma unroll
        for (int o = 16; o; o >>= 1) s += __shfl_xor_sync(0xFFFFFFFFu, s, o);
        float inv = 1.f / s;
        w[wh][lane] = e0 * inv;
        w[wh][lane + 32] = e1 * inv;
        w[wh][lane + 64] = e2 * inv;
        w[wh][lane + 96] = e3 * inv;
    }
    __syncthreads();

    float acc0 = 0.f, acc1 = 0.f, acc2 = 0.f, acc3 = 0.f;
    const float* hbase = g_h + (((size_t)(t << 10)) << 9) + tid;
    int j = 0;
    for (; j + 4 <= cnt; j += 4) {
        const float* p0 = hbase + ((size_t)nb[j] << 9);
        const float* p1 = hbase + ((size_t)nb[j + 1] << 9);
        const float* p2 = hbase + ((size_t)nb[j + 2] << 9);
        const float* p3 = hbase + ((size_t)nb[j + 3] << 9);
#pragma unroll
        for (int hh = 0; hh < 4; hh++) {
            acc0 += w[hh][j] * p0[hh << 7];
            acc1 += w[hh][j + 1] * p1[hh << 7];
            acc2 += w[hh][j + 2] * p2[hh << 7];
            acc3 += w[hh][j + 3] * p3[hh << 7];
        }
    }
    for (; j < cnt; j++) {
        const float* p0 = hbase + ((size_t)nb[j] << 9);
#pragma unroll
        for (int hh = 0; hh < 4; hh++) acc0 += w[hh][j] * p0[hh << 7];
    }
    float o = (acc0 + acc1 + acc2 + acc3) * 0.25f + bias[tid];
    xout[(size_t)row * 128 + tid] = fmaxf(o, 0.f);
}

// ---------------- transpose to sequence layout + sinusoidal PE ----------------
__global__ void to_seq(const float* __restrict__ xin) {
    int idx = blockIdx.x * 256 + threadIdx.x;
    int row = idx >> 7;
    int d = idx & 127;
    int t = row >> 10;
    int mm = row & 1023;
    float freq = expf(-(float)(d & ~1) * (9.210340371976184f / 128.f));
    float ang = (float)t * freq;
    float pe = (d & 1) ? cosf(ang) : sinf(ang);
    g_xs[((size_t)mm * Tt + t) * Hh + d] = xin[idx] + pe;
}

// ---------------- per-sequence attention (T=16, 4 heads of 32) ----------------
__global__ void attn_kernel(const float* __restrict__ Q, const float* __restrict__ K,
                            const float* __restrict__ V, float* __restrict__ O) {
    __shared__ float sq[16][128], sk[16][128], sv[16][128];
    int m = blockIdx.x;
    int tid = threadIdx.x;
    size_t base = (size_t)m * 16 * 128;
    for (int idx = tid; idx < 2048; idx += 128) {
        sq[idx >> 7][idx & 127] = Q[base + idx];
        sk[idx >> 7][idx & 127] = K[base + idx];
        sv[idx >> 7][idx & 127] = V[base + idx];
    }
    __syncthreads();
    if (tid < 64) {
        int h = tid >> 4, tq = tid & 15;
        const float scale = 0.17677669529663687f;
        float sc[16];
        float mx = -1e30f;
#pragma unroll
        for (int tk = 0; tk < 16; tk++) {
            float s = 0.f;
#pragma unroll
            for (int d = 0; d < 32; d++) s += sq[tq][h * 32 + d] * sk[tk][h * 32 + d];
            s *= scale;
            sc[tk] = s;
            mx = fmaxf(mx, s);
        }
        float sum = 0.f;
#pragma unroll
        for (int tk = 0; tk < 16; tk++) { sc[tk] = expf(sc[tk] - mx); sum += sc[tk]; }
        float inv = 1.f / sum;
#pragma unroll
        for (int d = 0; d < 32; d++) {
            float o = 0.f;
#pragma unroll
            for (int tk = 0; tk < 16; tk++) o += sc[tk] * sv[tk][h * 32 + d];
            O[base + (size_t)tq * 128 + h * 32 + d] = o * inv;
        }
    }
}

// ---------------- LayerNorm ----------------
__global__ void ln_kernel(const float* __restrict__ in, const float* __restrict__ s,
                          const float* __restrict__ b, float* __restrict__ out) {
    int row = blockIdx.x;
    int tid = threadIdx.x;
    __shared__ float red[8];
    float x = in[(size_t)row * 128 + tid];
    float sum = x;
#pragma unroll
    for (int o = 16; o; o >>= 1) sum += __shfl_xor_sync(0xFFFFFFFFu, sum, o);
    if ((tid & 31) == 0) red[tid >> 5] = sum;
    __syncthreads();
    float mean = (red[0] + red[1] + red[2] + red[3]) * (1.f / 128.f);
    float dd = x - mean;
    float qq = dd * dd;
#pragma unroll
    for (int o = 16; o; o >>= 1) qq += __shfl_xor_sync(0xFFFFFFFFu, qq, o);
    if ((tid & 31) == 0) red[4 + (tid >> 5)] = qq;
    __syncthreads();
    float var = (red[4] + red[5] + red[6] + red[7]) * (1.f / 128.f);
    out[(size_t)row * 128 + tid] = dd * rsqrtf(var + 1e-5f) * s[tid] + b[tid];
}

// ---------------- launcher ----------------
extern "C" void kernel_launch(void* const* d_in, const int* in_sizes, int n_in,
                              void* d_out, int out_size) {
    const unsigned char* ego = (const unsigned char*)d_in[0];
    const float* positions  = (const float*)d_in[1];
    const float* adjacency  = (const float*)d_in[2];
    const float* gat1_W     = (const float*)d_in[3];
    const float* gat1_asrc  = (const float*)d_in[4];
    const float* gat1_adst  = (const float*)d_in[5];
    const float* gat1_b     = (const float*)d_in[6];
    const float* gatW       = (const float*)d_in[7];
    const float* gat_asrc   = (const float*)d_in[8];
    const float* gat_adst   = (const float*)d_in[9];
    const float* gat_b      = (const float*)d_in[10];
    const float* Wqkv       = (const float*)d_in[11];
    const float* bqkv       = (const float*)d_in[12];
    const float* Wo         = (const float*)d_in[13];
    const float* bo         = (const float*)d_in[14];
    const float* ln1_s      = (const float*)d_in[15];
    const float* ln1_b      = (const float*)d_in[16];
    const float* ln2_s      = (const float*)d_in[17];
    const float* ln2_b      = (const float*)d_in[18];
    const float* Wff1       = (const float*)d_in[19];
    const float* bff1       = (const float*)d_in[20];
    const float* Wff2       = (const float*)d_in[21];
    const float* bff2       = (const float*)d_in[22];
    float* out = (float*)d_out;

    float *h, *xa, *xb, *xs, *q, *k, *v, *att, *r, *ff, *ss, *sd;
    __nv_bfloat16 *wh, *wl;
    cudaGetSymbolAddress((void**)&h,   g_h);
    cudaGetSymbolAddress((void**)&xa,  g_xa);
    cudaGetSymbolAddress((void**)&xb,  g_xb);
    cudaGetSymbolAddress((void**)&xs,  g_xs);
    cudaGetSymbolAddress((void**)&q,   g_q);
    cudaGetSymbolAddress((void**)&k,   g_k);
    cudaGetSymbolAddress((void**)&v,   g_v);
    cudaGetSymbolAddress((void**)&att, g_att);
    cudaGetSymbolAddress((void**)&r,   g_r);
    cudaGetSymbolAddress((void**)&ff,  g_ff);
    cudaGetSymbolAddress((void**)&ss,  g_ss);
    cudaGetSymbolAddress((void**)&sd,  g_sd);
    cudaGetSymbolAddress((void**)&wh,  g_wh);
    cudaGetSymbolAddress((void**)&wl,  g_wl);

    cudaFuncSetAttribute(gemm_tc<0, false, true>,  cudaFuncAttributeMaxDynamicSharedMemorySize, GSM_TOTAL);
    cudaFuncSetAttribute(gemm_tc<0, false, false>, cudaFuncAttributeMaxDynamicSharedMemorySize, GSM_TOTAL);
    cudaFuncSetAttribute(gemm_tc<0, true,  false>, cudaFuncAttributeMaxDynamicSharedMemorySize, GSM_TOTAL);
    cudaFuncSetAttribute(gemm_tc<1, false, false>, cudaFuncAttributeMaxDynamicSharedMemorySize, GSM_TOTAL);

    // Pre-split weights + edge structure
    split_weights<<<(WTOT + 255) / 256, 256>>>(gatW, Wqkv, Wo, Wff1, Wff2);
    mask_init<<<ROWS / 256, 256>>>(ego);
    build_nbr<<<ROWS * 4, 256>>>(adjacency);

    // GAT layer 0 (FIN=2)
    gat_proj0<<<ROWS * 512 / 256, 256>>>(positions, gat1_W);
    ssd_kernel<<<ROWS, 128>>>(gat1_asrc, gat1_adst);
    gat_agg<<<ROWS, 128>>>(gat1_b, xa);

    // GAT layers 1..5: HMMA GEMM (fused scores) + aggregation
    float* cur = xa;
    float* nxt = xb;
    for (int i = 0; i < 5; i++) {
        dim3 gp(4, ROWS / 128);
        gemm_tc<0, false, true><<<gp, 256, GSM_TOTAL>>>(
            cur, wh + OFF_GAT + (size_t)i * 65536, wl + OFF_GAT + (size_t)i * 65536,
            nullptr, nullptr, h, gat_asrc + i * 512, gat_adst + i * 512, ss, sd, 512, 128);
        gat_agg<<<ROWS, 128>>>(gat_b + i * 128, nxt);
        float* tmp = cur; cur = nxt; nxt = tmp;
    }

    to_seq<<<ROWS * 128 / 256, 256>>>(cur);

    dim3 g1(1, ROWS / 128);
    dim3 g2(4, ROWS / 128);
    for (int l = 0; l < NL_TR; l++) {
        size_t oq = OFF_QKV + (size_t)(l * 3 + 0) * 16384;
        size_t ok = OFF_QKV + (size_t)(l * 3 + 1) * 16384;
        size_t ov = OFF_QKV + (size_t)(l * 3 + 2) * 16384;
        gemm_tc<0, false, false><<<g1, 256, GSM_TOTAL>>>(xs, wh + oq, wl + oq,
            bqkv + (l * 3 + 0) * 128, nullptr, q, nullptr, nullptr, nullptr, nullptr, 128, 128);
        gemm_tc<0, false, false><<<g1, 256, GSM_TOTAL>>>(xs, wh + ok, wl + ok,
            bqkv + (l * 3 + 1) * 128, nullptr, k, nullptr, nullptr, nullptr, nullptr, 128, 128);
        gemm_tc<0, false, false><<<g1, 256, GSM_TOTAL>>>(xs, wh + ov, wl + ov,
            bqkv + (l * 3 + 2) * 128, nullptr, v, nullptr, nullptr, nullptr, nullptr, 128, 128);
        attn_kernel<<<Mm, 128>>>(q, k, v, att);
        size_t owo = OFF_WO + (size_t)l * 16384;
        gemm_tc<0, true, false><<<g1, 256, GSM_TOTAL>>>(att, wh + owo, wl + owo,
            bo + l * 128, xs, r, nullptr, nullptr, nullptr, nullptr, 128, 128);
        ln_kernel<<<ROWS, 128>>>(r, ln1_s + l * 128, ln1_b + l * 128, xs);
        size_t of1 = OFF_FF1 + (size_t)l * 65536;
        gemm_tc<1, false, false><<<g2, 256, GSM_TOTAL>>>(xs, wh + of1, wl + of1,
            bff1 + l * 512, nullptr, ff, nullptr, nullptr, nullptr, nullptr, 512, 128);
        size_t of2 = OFF_FF2 + (size_t)l * 65536;
        gemm_tc<0, true, false><<<g1, 256, GSM_TOTAL>>>(ff, wh + of2, wl + of2,
            bff2 + l * 128, xs, r, nullptr, nullptr, nullptr, nullptr, 128, 512);
        float* lnout = (l == NL_TR - 1) ? out : xs;
        ln_kernel<<<ROWS, 128>>>(r, ln2_s + l * 128, ln2_b + l * 128, lnout);
    }
}

// round 4
// speedup vs baseline: 1.8023x; 1.6808x over previous
#include <cuda_runtime.h>
#include <cuda_bf16.h>
#include <math.h>

// Problem dims
#define Tt 16
#define Mm 1024
#define Hh 128
#define NHEADS 4
#define ROWS (Tt * Mm)   // 16384
#define MAXD 128
#define NL_TR 5

// ---------------- scratch (device globals; no allocations) ----------------
__device__ float g_h[ROWS * 512];          // GAT projections / transformer QKV (384)
__device__ float g_xa[ROWS * Hh];
__device__ float g_xb[ROWS * Hh];
__device__ float g_ss[ROWS * NHEADS];
__device__ float g_sd[ROWS * NHEADS];
__device__ unsigned char g_m[ROWS];
__device__ int g_cnt[ROWS];
__device__ unsigned short g_nbr[ROWS * MAXD];
__device__ float g_xs[ROWS * Hh];
__device__ float g_att[ROWS * Hh];
__device__ float g_ff[ROWS * 512];

// Pre-split weights (bf16 hi/lo, transposed to [N, K])
#define WTOT 1310720
#define OFF_GAT 0
#define OFF_QKV 327680
#define OFF_WO  573440
#define OFF_FF1 655360
#define OFF_FF2 983040
__device__ __nv_bfloat16 g_wh[WTOT];
__device__ __nv_bfloat16 g_wl[WTOT];

__device__ __forceinline__ unsigned smem_u32(const void* p) {
    unsigned a;
    asm("{ .reg .u64 t; cvta.to.shared.u64 t, %1; cvt.u32.u64 %0, t; }" : "=r"(a) : "l"(p));
    return a;
}
__device__ __forceinline__ void ldmat4(unsigned& r0, unsigned& r1, unsigned& r2, unsigned& r3, unsigned addr) {
    asm volatile("ldmatrix.sync.aligned.m8n8.x4.shared.b16 {%0,%1,%2,%3}, [%4];"
        : "=r"(r0), "=r"(r1), "=r"(r2), "=r"(r3) : "r"(addr));
}
__device__ __forceinline__ void mma16816(float* c, unsigned a0, unsigned a1, unsigned a2, unsigned a3,
                                         unsigned b0, unsigned b1) {
    asm volatile("mma.sync.aligned.m16n8k16.row.col.f32.bf16.bf16.f32 "
        "{%0,%1,%2,%3}, {%4,%5,%6,%7}, {%8,%9}, {%0,%1,%2,%3};"
        : "+f"(c[0]), "+f"(c[1]), "+f"(c[2]), "+f"(c[3])
        : "r"(a0), "r"(a1), "r"(a2), "r"(a3), "r"(b0), "r"(b1));
}

// SMEM layout: 4 tile buffers (A hi/lo, B hi/lo), 128 rows x 72 bf16 (144B stride)
#define TROW 144
#define TBUF (128 * TROW)     // 18432 B
#define SM_AHI 0
#define SM_ALO TBUF
#define SM_BHI (2 * TBUF)
#define SM_BLO (3 * TBUF)
#define GSM_TOTAL (4 * TBUF)  // 73728 B (stage 128*132*4=67584 fits)

// ---------------- HMMA GEMM: C[128x128 tile] = act(A @ B^T + bias (+R)) (+fused LN) ----------------
template <int ACT, bool RESID, bool SCORES, bool LNORM>
__global__ void __launch_bounds__(256)
gemm_tc(const float* __restrict__ A, const __nv_bfloat16* __restrict__ Bh,
        const __nv_bfloat16* __restrict__ Bl, const float* __restrict__ bias,
        const float* __restrict__ Rr, float* __restrict__ C,
        const float* __restrict__ asrc, const float* __restrict__ adst,
        float* __restrict__ gss, float* __restrict__ gsd,
        const float* __restrict__ ls, const float* __restrict__ lb, int Nt, int Kt) {
    extern __shared__ char smem[];
    const unsigned sb = smem_u32(smem);
    const int tid = threadIdx.x;
    const int wid = tid >> 5, lane = tid & 31;
    const int wr = wid >> 1, wc = wid & 1;
    const int row0 = blockIdx.y * 128;
    const int col0 = blockIdx.x * 128;

    float acc[2][8][4];
#pragma unroll
    for (int mt = 0; mt < 2; mt++)
#pragma unroll
        for (int nt = 0; nt < 8; nt++)
#pragma unroll
            for (int e = 0; e < 4; e++) acc[mt][nt][e] = 0.f;

    const int ltile = lane >> 3, lrow = lane & 7;

    for (int kc = 0; kc < Kt; kc += 64) {
        for (int i = tid; i < 128 * 16; i += 256) {
            int r = i >> 4, q = i & 15;
            float4 v = *(const float4*)(A + (size_t)(row0 + r) * Kt + kc + q * 4);
            __nv_bfloat16 h0 = __float2bfloat16(v.x), h1 = __float2bfloat16(v.y);
            __nv_bfloat16 h2 = __float2bfloat16(v.z), h3 = __float2bfloat16(v.w);
            __nv_bfloat16 l0 = __float2bfloat16(v.x - __bfloat162float(h0));
            __nv_bfloat16 l1 = __float2bfloat16(v.y - __bfloat162float(h1));
            __nv_bfloat16 l2 = __float2bfloat16(v.z - __bfloat162float(h2));
            __nv_bfloat16 l3 = __float2bfloat16(v.w - __bfloat162float(h3));
            uint2 uh, ul;
            uh.x = (unsigned)__bfloat16_as_ushort(h0) | ((unsigned)__bfloat16_as_ushort(h1) << 16);
            uh.y = (unsigned)__bfloat16_as_ushort(h2) | ((unsigned)__bfloat16_as_ushort(h3) << 16);
            ul.x = (unsigned)__bfloat16_as_ushort(l0) | ((unsigned)__bfloat16_as_ushort(l1) << 16);
            ul.y = (unsigned)__bfloat16_as_ushort(l2) | ((unsigned)__bfloat16_as_ushort(l3) << 16);
            int off = r * TROW + q * 8;
            *(uint2*)(smem + SM_AHI + off) = uh;
            *(uint2*)(smem + SM_ALO + off) = ul;
        }
        for (int i = tid; i < 128 * 8; i += 256) {
            int n = i >> 3, q = i & 7;
            size_t ga = (size_t)(col0 + n) * Kt + kc + q * 8;
            uint4 vh = *(const uint4*)(Bh + ga);
            uint4 vl = *(const uint4*)(Bl + ga);
            int off = n * TROW + q * 16;
            *(uint4*)(smem + SM_BHI + off) = vh;
            *(uint4*)(smem + SM_BLO + off) = vl;
        }
        __syncthreads();

#pragma unroll
        for (int ks = 0; ks < 4; ks++) {
            unsigned ah[2][4], al[2][4];
#pragma unroll
            for (int mt = 0; mt < 2; mt++) {
                int row = wr * 32 + mt * 16 + lrow + (ltile & 1) * 8;
                int kcol = ks * 16 + (ltile >> 1) * 8;
                unsigned off = (unsigned)(row * TROW + kcol * 2);
                ldmat4(ah[mt][0], ah[mt][1], ah[mt][2], ah[mt][3], sb + SM_AHI + off);
                ldmat4(al[mt][0], al[mt][1], al[mt][2], al[mt][3], sb + SM_ALO + off);
            }
#pragma unroll
            for (int g = 0; g < 4; g++) {
                int n = wc * 64 + g * 16 + lrow + (ltile >> 1) * 8;
                int kcol = ks * 16 + (ltile & 1) * 8;
                unsigned off = (unsigned)(n * TROW + kcol * 2);
                unsigned bh[4], bl[4];
                ldmat4(bh[0], bh[1], bh[2], bh[3], sb + SM_BHI + off);
                ldmat4(bl[0], bl[1], bl[2], bl[3], sb + SM_BLO + off);
#pragma unroll
                for (int mt = 0; mt < 2; mt++)
#pragma unroll
                    for (int half = 0; half < 2; half++) {
                        float* cc = acc[mt][g * 2 + half];
                        mma16816(cc, ah[mt][0], ah[mt][1], ah[mt][2], ah[mt][3],
                                 bh[half * 2], bh[half * 2 + 1]);
                        mma16816(cc, ah[mt][0], ah[mt][1], ah[mt][2], ah[mt][3],
                                 bl[half * 2], bl[half * 2 + 1]);
                        mma16816(cc, al[mt][0], al[mt][1], al[mt][2], al[mt][3],
                                 bh[half * 2], bh[half * 2 + 1]);
                    }
            }
        }
        __syncthreads();
    }

    // stage accumulators to smem (stride 132 floats)
    float* stage = (float*)smem;
#pragma unroll
    for (int mt = 0; mt < 2; mt++)
#pragma unroll
        for (int nt = 0; nt < 8; nt++) {
            int row = wr * 32 + mt * 16 + (lane >> 2);
            int col = wc * 64 + nt * 8 + (lane & 3) * 2;
            float2 v0 = make_float2(acc[mt][nt][0], acc[mt][nt][1]);
            float2 v1 = make_float2(acc[mt][nt][2], acc[mt][nt][3]);
            *(float2*)(stage + (size_t)row * 132 + col) = v0;
            *(float2*)(stage + (size_t)(row + 8) * 132 + col) = v1;
        }
    __syncthreads();

    if (LNORM) {
        // Nt==128, grid.x==1: full rows owned by this CTA -> fused bias+residual+LayerNorm
        const int c = lane * 4;
        float4 bb = *(const float4*)(bias + c);
        float4 sv = *(const float4*)(ls + c);
        float4 bv = *(const float4*)(lb + c);
#pragma unroll 4
        for (int rr = 0; rr < 16; rr++) {
            int r = wid * 16 + rr;
            float4 v = *(float4*)(stage + (size_t)r * 132 + c);
            float4 res = *(const float4*)(Rr + (size_t)(row0 + r) * 128 + c);
            v.x += bb.x + res.x; v.y += bb.y + res.y;
            v.z += bb.z + res.z; v.w += bb.w + res.w;
            float s = v.x + v.y + v.z + v.w;
#pragma unroll
            for (int o = 16; o; o >>= 1) s += __shfl_xor_sync(0xFFFFFFFFu, s, o);
            float mean = s * (1.f / 128.f);
            float dx = v.x - mean, dy = v.y - mean, dz = v.z - mean, dw = v.w - mean;
            float qq = dx * dx + dy * dy + dz * dz + dw * dw;
#pragma unroll
            for (int o = 16; o; o >>= 1) qq += __shfl_xor_sync(0xFFFFFFFFu, qq, o);
            float rstd = rsqrtf(qq * (1.f / 128.f) + 1e-5f);
            float4 ov;
            ov.x = dx * rstd * sv.x + bv.x;
            ov.y = dy * rstd * sv.y + bv.y;
            ov.z = dz * rstd * sv.z + bv.z;
            ov.w = dw * rstd * sv.w + bv.w;
            *(float4*)(C + (size_t)(row0 + r) * 128 + c) = ov;
        }
    } else {
        for (int i = tid; i < 128 * 32; i += 256) {
            int r = i >> 5, q = i & 31;
            int c = q * 4;
            float4 v = *(float4*)(stage + (size_t)r * 132 + c);
            if (bias) {
                v.x += bias[col0 + c];
                v.y += bias[col0 + c + 1];
                v.z += bias[col0 + c + 2];
                v.w += bias[col0 + c + 3];
            }
            if (RESID) {
                float4 rr = *(const float4*)(Rr + (size_t)(row0 + r) * Nt + col0 + c);
                v.x += rr.x; v.y += rr.y; v.z += rr.z; v.w += rr.w;
            }
            if (ACT == 1) {
                v.x = fmaxf(v.x, 0.f); v.y = fmaxf(v.y, 0.f);
                v.z = fmaxf(v.z, 0.f); v.w = fmaxf(v.w, 0.f);
            }
            *(float4*)(C + (size_t)(row0 + r) * Nt + col0 + c) = v;
        }
    }

    if (SCORES && tid < 128) {
        int r = tid;
        float s1 = 0.f, s2 = 0.f;
        const float* as = asrc + col0;
        const float* ad = adst + col0;
        const float* sp = stage + (size_t)r * 132;
#pragma unroll 8
        for (int c = 0; c < 128; c++) {
            float hv = sp[c];
            s1 += hv * as[c];
            s2 += hv * ad[c];
        }
        gss[(size_t)(row0 + r) * 4 + blockIdx.x] = s1;
        gsd[(size_t)(row0 + r) * 4 + blockIdx.x] = s2;
    }
}

// ---------------- weight pre-split; QKV packed per-layer [384, 128] ----------------
__global__ void split_weights(const float* __restrict__ gatW, const float* __restrict__ Wqkv,
                              const float* __restrict__ Wo, const float* __restrict__ Wff1,
                              const float* __restrict__ Wff2) {
    int idx = blockIdx.x * 256 + threadIdx.x;
    if (idx >= WTOT) return;
    float v;
    if (idx < OFF_QKV) {                    // gatW [128,512] -> [512,128]
        int i = idx >> 16, r = idx & 65535;
        int n = r >> 7, k = r & 127;
        v = gatW[(i << 16) + k * 512 + n];
    } else if (idx < OFF_WO) {              // Wqkv packed [l][384][128]
        int r0 = idx - OFF_QKV;
        int l = r0 / 49152;
        int rem = r0 - l * 49152;
        int n = rem >> 7, k = rem & 127;
        int s = n >> 7, nc = n & 127;
        v = Wqkv[((l * 3 + s) << 14) + k * 128 + nc];
    } else if (idx < OFF_FF1) {             // Wo
        int r0 = idx - OFF_WO;
        int i = r0 >> 14, r = r0 & 16383;
        int n = r >> 7, k = r & 127;
        v = Wo[(i << 14) + k * 128 + n];
    } else if (idx < OFF_FF2) {             // Wff1 [128,512] -> [512,128]
        int r0 = idx - OFF_FF1;
        int i = r0 >> 16, r = r0 & 65535;
        int n = r >> 7, k = r & 127;
        v = Wff1[(i << 16) + k * 512 + n];
    } else {                                // Wff2 [512,128] -> [128,512]
        int r0 = idx - OFF_FF2;
        int i = r0 >> 16, r = r0 & 65535;
        int n = r >> 9, k = r & 511;
        v = Wff2[(i << 16) + k * 128 + n];
    }
    __nv_bfloat16 h = __float2bfloat16(v);
    g_wh[idx] = h;
    g_wl[idx] = __float2bfloat16(v - __bfloat162float(h));
}

// ---------------- mask + self-loop init ----------------
__global__ void mask_init(const unsigned char* __restrict__ ego) {
    int idx = blockIdx.x * 256 + threadIdx.x;
    if (idx >= ROWS) return;
    int t = idx >> 10;
    int mm = idx & 1023;
    int b = mm >> 8;
    int n = mm & 255;
    unsigned char v = ego[(b * Tt + t) * 256 + n] ? 1 : 0;
    g_m[idx] = v;
    g_cnt[idx] = v ? 1 : 0;
    g_nbr[idx * MAXD] = (unsigned short)mm;
}

// ---------------- neighbor-list build ----------------
__global__ void build_nbr(const float* __restrict__ A) {
    int tj = blockIdx.x >> 2;
    int i = ((blockIdx.x & 3) << 8) + threadIdx.x;
    if (!g_m[tj]) return;
    int t = tj >> 10;
    int j = tj & 1023;
    if (i == j) return;
    float a = A[(size_t)tj * 1024 + i];
    int ti = (t << 10) + i;
    if (a != 0.f && g_m[ti]) {
        int pos = atomicAdd(&g_cnt[ti], 1);
        if (pos < MAXD) g_nbr[ti * MAXD + pos] = (unsigned short)j;
    }
}

// ---------------- GAT layer-0: fused projection (FIN=2) + src/dst scores ----------------
__global__ void gat0_fused(const float* __restrict__ x, const float* __restrict__ W,
                           const float* __restrict__ asrc, const float* __restrict__ adst) {
    int row = blockIdx.x;
    int d = threadIdx.x;         // 128
    int lane = d & 31, wrp = d >> 5;
    float x0 = x[row * 2], x1 = x[row * 2 + 1];
    __shared__ float red[4][8];
    float hv[4];
    float s1[4], s2[4];
#pragma unroll
    for (int hh = 0; hh < 4; hh++) {
        int c = hh * 128 + d;
        float v = x0 * W[c] + x1 * W[512 + c];
        hv[hh] = v;
        g_h[(size_t)row * 512 + c] = v;
        s1[hh] = v * asrc[c];
        s2[hh] = v * adst[c];
    }
#pragma unroll
    for (int hh = 0; hh < 4; hh++) {
#pragma unroll
        for (int o = 16; o; o >>= 1) {
            s1[hh] += __shfl_xor_sync(0xFFFFFFFFu, s1[hh], o);
            s2[hh] += __shfl_xor_sync(0xFFFFFFFFu, s2[hh], o);
        }
    }
    if (lane == 0) {
#pragma unroll
        for (int hh = 0; hh < 4; hh++) {
            red[wrp][hh] = s1[hh];
            red[wrp][4 + hh] = s2[hh];
        }
    }
    __syncthreads();
    if (d < 8) {
        float s = red[0][d] + red[1][d] + red[2][d] + red[3][d];
        if (d < 4) g_ss[row * 4 + d] = s;
        else g_sd[row * 4 + (d - 4)] = s;
    }
}

// ---------------- sparse segment-softmax + aggregation ----------------
__global__ void gat_agg(const float* __restrict__ bias, float* __restrict__ xout) {
    int row = blockIdx.x;
    int tid = threadIdx.x;
    if (!g_m[row]) { xout[(size_t)row * 128 + tid] = 0.f; return; }
    int t = row >> 10;

    __shared__ unsigned short nb[MAXD];
    __shared__ float w[4][MAXD];

    int cnt = g_cnt[row];
    if (cnt > MAXD) cnt = MAXD;
    if (tid < cnt) nb[tid] = g_nbr[(size_t)row * MAXD + tid];

    if (tid < cnt) {
        int jr = (t << 10) + nb[tid];
#pragma unroll
        for (int hh = 0; hh < 4; hh++) {
            float z = g_sd[row * 4 + hh] + g_ss[jr * 4 + hh];
            w[hh][tid] = (z > 0.f) ? z : 0.2f * z;
        }
    } else {
#pragma unroll
        for (int hh = 0; hh < 4; hh++) w[hh][tid] = -INFINITY;
    }
    __syncthreads();

    {
        int wh = tid >> 5, lane = tid & 31;
        float v0 = w[wh][lane], v1 = w[wh][lane + 32], v2 = w[wh][lane + 64], v3 = w[wh][lane + 96];
        float mx = fmaxf(fmaxf(v0, v1), fmaxf(v2, v3));
#pragma unroll
        for (int o = 16; o; o >>= 1) mx = fmaxf(mx, __shfl_xor_sync(0xFFFFFFFFu, mx, o));
        float e0 = expf(v0 - mx), e1 = expf(v1 - mx), e2 = expf(v2 - mx), e3 = expf(v3 - mx);
        float s = e0 + e1 + e2 + e3;
#pragma unroll
        for (int o = 16; o; o >>= 1) s += __shfl_xor_sync(0xFFFFFFFFu, s, o);
        float inv = 1.f / s;
        w[wh][lane] = e0 * inv;
        w[wh][lane + 32] = e1 * inv;
        w[wh][lane + 64] = e2 * inv;
        w[wh][lane + 96] = e3 * inv;
    }
    __syncthreads();

    float acc0 = 0.f, acc1 = 0.f, acc2 = 0.f, acc3 = 0.f;
    const float* hbase = g_h + (((size_t)(t << 10)) << 9) + tid;
    int j = 0;
    for (; j + 4 <= cnt; j += 4) {
        const float* p0 = hbase + ((size_t)nb[j] << 9);
        const float* p1 = hbase + ((size_t)nb[j + 1] << 9);
        const float* p2 = hbase + ((size_t)nb[j + 2] << 9);
        const float* p3 = hbase + ((size_t)nb[j + 3] << 9);
#pragma unroll
        for (int hh = 0; hh < 4; hh++) {
            acc0 += w[hh][j] * p0[hh << 7];
            acc1 += w[hh][j + 1] * p1[hh << 7];
            acc2 += w[hh][j + 2] * p2[hh << 7];
            acc3 += w[hh][j + 3] * p3[hh << 7];
        }
    }
    for (; j < cnt; j++) {
        const float* p0 = hbase + ((size_t)nb[j] << 9);
#pragma unroll
        for (int hh = 0; hh < 4; hh++) acc0 += w[hh][j] * p0[hh << 7];
    }
    float o = (acc0 + acc1 + acc2 + acc3) * 0.25f + bias[tid];
    xout[(size_t)row * 128 + tid] = fmaxf(o, 0.f);
}

// ---------------- transpose to sequence layout + sinusoidal PE ----------------
__global__ void to_seq(const float* __restrict__ xin) {
    int idx = blockIdx.x * 256 + threadIdx.x;
    int row = idx >> 7;
    int d = idx & 127;
    int t = row >> 10;
    int mm = row & 1023;
    float freq = expf(-(float)(d & ~1) * (9.210340371976184f / 128.f));
    float ang = (float)t * freq;
    float pe = (d & 1) ? cosf(ang) : sinf(ang);
    g_xs[((size_t)mm * Tt + t) * Hh + d] = xin[idx] + pe;
}

// ---------------- per-sequence attention (T=16, 4 heads of 32), packed QKV input ----------------
__global__ void attn_kernel(const float* __restrict__ QKV, float* __restrict__ O) {
    __shared__ float sq[16][128], sk[16][128], sv[16][128];
    int m = blockIdx.x;
    int tid = threadIdx.x;   // 128
    size_t base = (size_t)m * 16 * 384;
    for (int idx = tid; idx < 2048; idx += 128) {
        int t = idx >> 7, d = idx & 127;
        size_t p = base + (size_t)t * 384 + d;
        sq[t][d] = QKV[p];
        sk[t][d] = QKV[p + 128];
        sv[t][d] = QKV[p + 256];
    }
    __syncthreads();
    int h = tid >> 5;
    int tq = (tid >> 1) & 15;
    int half = tid & 1;
    const float scale = 0.17677669529663687f;
    float sc[16];
    float mx = -1e30f;
#pragma unroll
    for (int tk = 0; tk < 16; tk++) {
        float s = 0.f;
#pragma unroll
        for (int dd = 0; dd < 16; dd++) {
            int d = half * 16 + dd;
            s += sq[tq][h * 32 + d] * sk[tk][h * 32 + d];
        }
        s += __shfl_xor_sync(0xFFFFFFFFu, s, 1);
        s *= scale;
        sc[tk] = s;
        mx = fmaxf(mx, s);
    }
    float sum = 0.f;
#pragma unroll
    for (int tk = 0; tk < 16; tk++) { sc[tk] = expf(sc[tk] - mx); sum += sc[tk]; }
    float inv = 1.f / sum;
    size_t ob = (size_t)m * 16 * 128 + (size_t)tq * 128 + h * 32 + half * 16;
#pragma unroll
    for (int dd = 0; dd < 16; dd++) {
        int d = half * 16 + dd;
        float o = 0.f;
#pragma unroll
        for (int tk = 0; tk < 16; tk++) o += sc[tk] * sv[tk][h * 32 + d];
        O[ob + dd] = o * inv;
    }
}

// ---------------- launcher ----------------
extern "C" void kernel_launch(void* const* d_in, const int* in_sizes, int n_in,
                              void* d_out, int out_size) {
    const unsigned char* ego = (const unsigned char*)d_in[0];
    const float* positions  = (const float*)d_in[1];
    const float* adjacency  = (const float*)d_in[2];
    const float* gat1_W     = (const float*)d_in[3];
    const float* gat1_asrc  = (const float*)d_in[4];
    const float* gat1_adst  = (const float*)d_in[5];
    const float* gat1_b     = (const float*)d_in[6];
    const float* gatW       = (const float*)d_in[7];
    const float* gat_asrc   = (const float*)d_in[8];
    const float* gat_adst   = (const float*)d_in[9];
    const float* gat_b      = (const float*)d_in[10];
    const float* Wqkv       = (const float*)d_in[11];
    const float* bqkv       = (const float*)d_in[12];
    const float* Wo         = (const float*)d_in[13];
    const float* bo         = (const float*)d_in[14];
    const float* ln1_s      = (const float*)d_in[15];
    const float* ln1_b      = (const float*)d_in[16];
    const float* ln2_s      = (const float*)d_in[17];
    const float* ln2_b      = (const float*)d_in[18];
    const float* Wff1       = (const float*)d_in[19];
    const float* bff1       = (const float*)d_in[20];
    const float* Wff2       = (const float*)d_in[21];
    const float* bff2       = (const float*)d_in[22];
    float* out = (float*)d_out;

    float *h, *xa, *xb, *xs, *att, *ff, *ss, *sd;
    __nv_bfloat16 *wh, *wl;
    cudaGetSymbolAddress((void**)&h,   g_h);
    cudaGetSymbolAddress((void**)&xa,  g_xa);
    cudaGetSymbolAddress((void**)&xb,  g_xb);
    cudaGetSymbolAddress((void**)&xs,  g_xs);
    cudaGetSymbolAddress((void**)&att, g_att);
    cudaGetSymbolAddress((void**)&ff,  g_ff);
    cudaGetSymbolAddress((void**)&ss,  g_ss);
    cudaGetSymbolAddress((void**)&sd,  g_sd);
    cudaGetSymbolAddress((void**)&wh,  g_wh);
    cudaGetSymbolAddress((void**)&wl,  g_wl);

    cudaFuncSetAttribute(gemm_tc<0, false, true,  false>, cudaFuncAttributeMaxDynamicSharedMemorySize, GSM_TOTAL);
    cudaFuncSetAttribute(gemm_tc<0, false, false, false>, cudaFuncAttributeMaxDynamicSharedMemorySize, GSM_TOTAL);
    cudaFuncSetAttribute(gemm_tc<0, true,  false, true >, cudaFuncAttributeMaxDynamicSharedMemorySize, GSM_TOTAL);
    cudaFuncSetAttribute(gemm_tc<1, false, false, false>, cudaFuncAttributeMaxDynamicSharedMemorySize, GSM_TOTAL);

    split_weights<<<(WTOT + 255) / 256, 256>>>(gatW, Wqkv, Wo, Wff1, Wff2);
    mask_init<<<ROWS / 256, 256>>>(ego);
    build_nbr<<<ROWS * 4, 256>>>(adjacency);

    // GAT layer 0 (FIN=2): fused projection + scores
    gat0_fused<<<ROWS, 128>>>(positions, gat1_W, gat1_asrc, gat1_adst);
    gat_agg<<<ROWS, 128>>>(gat1_b, xa);

    // GAT layers 1..5
    float* cur = xa;
    float* nxt = xb;
    for (int i = 0; i < 5; i++) {
        dim3 gp(4, ROWS / 128);
        gemm_tc<0, false, true, false><<<gp, 256, GSM_TOTAL>>>(
            cur, wh + OFF_GAT + (size_t)i * 65536, wl + OFF_GAT + (size_t)i * 65536,
            nullptr, nullptr, h, gat_asrc + i * 512, gat_adst + i * 512, ss, sd,
            nullptr, nullptr, 512, 128);
        gat_agg<<<ROWS, 128>>>(gat_b + i * 128, nxt);
        float* tmp = cur; cur = nxt; nxt = tmp;
    }

    to_seq<<<ROWS * 128 / 256, 256>>>(cur);

    dim3 g1(1, ROWS / 128);
    dim3 g2(4, ROWS / 128);
    dim3 gq(3, ROWS / 128);
    for (int l = 0; l < NL_TR; l++) {
        // fused QKV GEMM -> g_h [ROWS][384]
        size_t oq = OFF_QKV + (size_t)l * 49152;
        gemm_tc<0, false, false, false><<<gq, 256, GSM_TOTAL>>>(xs, wh + oq, wl + oq,
            bqkv + l * 384, nullptr, h, nullptr, nullptr, nullptr, nullptr,
            nullptr, nullptr, 384, 128);
        attn_kernel<<<Mm, 128>>>(h, att);
        // Wo GEMM + bias + residual + LayerNorm1 fused
        size_t owo = OFF_WO + (size_t)l * 16384;
        gemm_tc<0, true, false, true><<<g1, 256, GSM_TOTAL>>>(att, wh + owo, wl + owo,
            bo + l * 128, xs, xs, nullptr, nullptr, nullptr, nullptr,
            ln1_s + l * 128, ln1_b + l * 128, 128, 128);
        // FF1 GEMM + ReLU
        size_t of1 = OFF_FF1 + (size_t)l * 65536;
        gemm_tc<1, false, false, false><<<g2, 256, GSM_TOTAL>>>(xs, wh + of1, wl + of1,
            bff1 + l * 512, nullptr, ff, nullptr, nullptr, nullptr, nullptr,
            nullptr, nullptr, 512, 128);
        // FF2 GEMM + bias + residual + LayerNorm2 fused
        size_t of2 = OFF_FF2 + (size_t)l * 65536;
        float* lnout = (l == NL_TR - 1) ? out : xs;
        gemm_tc<0, true, false, true><<<g1, 256, GSM_TOTAL>>>(ff, wh + of2, wl + of2,
            bff2 + l * 128, xs, lnout, nullptr, nullptr, nullptr, nullptr,
            ln2_s + l * 128, ln2_b + l * 128, 128, 512);
    }
}

// round 5
// speedup vs baseline: 1.9659x; 1.0908x over previous
#include <cuda_runtime.h>
#include <cuda_bf16.h>
#include <math.h>

// Problem dims
#define Tt 16
#define Mm 1024
#define Hh 128
#define NHEADS 4
#define ROWS (Tt * Mm)   // 16384
#define MAXD 128
#define NL_TR 5

// ---------------- scratch (device globals; no allocations) ----------------
__device__ float g_h[ROWS * 512];          // GAT projections (512) / transformer QKV (384) fp32
__device__ float g_ss[ROWS * NHEADS];
__device__ float g_sd[ROWS * NHEADS];
__device__ unsigned char g_m[ROWS];
__device__ int g_cnt[ROWS];
__device__ unsigned short g_nbr[ROWS * MAXD];
__device__ float g_xs[ROWS * Hh];          // fp32 (residual use)
// planar bf16 hi/lo activations (GEMM A operands)
__device__ __nv_bfloat16 g_xah[ROWS * Hh], g_xal[ROWS * Hh];
__device__ __nv_bfloat16 g_xbh[ROWS * Hh], g_xbl[ROWS * Hh];
__device__ __nv_bfloat16 g_xsh[ROWS * Hh], g_xsl[ROWS * Hh];
__device__ __nv_bfloat16 g_atth[ROWS * Hh], g_attl[ROWS * Hh];
__device__ __nv_bfloat16 g_ffh[ROWS * 512], g_ffl[ROWS * 512];

// Pre-split weights (bf16 hi/lo, transposed to [N, K]); QKV packed [l][384][128]
#define WTOT 1310720
#define OFF_GAT 0
#define OFF_QKV 327680
#define OFF_WO  573440
#define OFF_FF1 655360
#define OFF_FF2 983040
__device__ __nv_bfloat16 g_wh[WTOT];
__device__ __nv_bfloat16 g_wl[WTOT];

__device__ __forceinline__ unsigned smem_u32(const void* p) {
    unsigned a;
    asm("{ .reg .u64 t; cvta.to.shared.u64 t, %1; cvt.u32.u64 %0, t; }" : "=r"(a) : "l"(p));
    return a;
}
__device__ __forceinline__ void ldmat4(unsigned& r0, unsigned& r1, unsigned& r2, unsigned& r3, unsigned addr) {
    asm volatile("ldmatrix.sync.aligned.m8n8.x4.shared.b16 {%0,%1,%2,%3}, [%4];"
        : "=r"(r0), "=r"(r1), "=r"(r2), "=r"(r3) : "r"(addr));
}
__device__ __forceinline__ void mma16816(float* c, unsigned a0, unsigned a1, unsigned a2, unsigned a3,
                                         unsigned b0, unsigned b1) {
    asm volatile("mma.sync.aligned.m16n8k16.row.col.f32.bf16.bf16.f32 "
        "{%0,%1,%2,%3}, {%4,%5,%6,%7}, {%8,%9}, {%0,%1,%2,%3};"
        : "+f"(c[0]), "+f"(c[1]), "+f"(c[2]), "+f"(c[3])
        : "r"(a0), "r"(a1), "r"(a2), "r"(a3), "r"(b0), "r"(b1));
}
__device__ __forceinline__ void cpa16(unsigned dst, const void* src) {
    asm volatile("cp.async.ca.shared.global [%0], [%1], 16;" :: "r"(dst), "l"(src));
}
#define CPA_COMMIT() asm volatile("cp.async.commit_group;" ::: "memory")
#define CPA_WAIT1() asm volatile("cp.async.wait_group 1;" ::: "memory")
#define CPA_WAIT0() asm volatile("cp.async.wait_group 0;" ::: "memory")

__device__ __forceinline__ unsigned pack_hi2(float a, float b) {
    __nv_bfloat16 ha = __float2bfloat16(a), hb = __float2bfloat16(b);
    return (unsigned)__bfloat16_as_ushort(ha) | ((unsigned)__bfloat16_as_ushort(hb) << 16);
}
__device__ __forceinline__ unsigned pack_lo2(float a, float b) {
    __nv_bfloat16 ha = __float2bfloat16(a), hb = __float2bfloat16(b);
    float la = a - __bfloat162float(ha), lb2 = b - __bfloat162float(hb);
    __nv_bfloat16 qa = __float2bfloat16(la), qb = __float2bfloat16(lb2);
    return (unsigned)__bfloat16_as_ushort(qa) | ((unsigned)__bfloat16_as_ushort(qb) << 16);
}

// SMEM: 2 stages x 4 planes (Ahi, Alo, Bhi, Blo), each 128 rows x 64 bf16 (144B stride)
#define TROW 144
#define PBUF (128 * TROW)       // 18432
#define STAGE (4 * PBUF)        // 73728
#define P_AHI 0
#define P_ALO PBUF
#define P_BHI (2 * PBUF)
#define P_BLO (3 * PBUF)
#define GSM_TOTAL (2 * STAGE)   // 147456

// ---------------- HMMA GEMM, planar bf16 A/B, cp.async double-buffered ----------------
template <int ACT, bool RESID, bool SCORES, bool LNORM>
__global__ void __launch_bounds__(256)
gemm_tc(const __nv_bfloat16* __restrict__ Ah, const __nv_bfloat16* __restrict__ Al,
        const __nv_bfloat16* __restrict__ Bh, const __nv_bfloat16* __restrict__ Bl,
        const float* __restrict__ bias, const float* __restrict__ Rr,
        float* __restrict__ C, __nv_bfloat16* __restrict__ Ch, __nv_bfloat16* __restrict__ Cl,
        const float* __restrict__ asrc, const float* __restrict__ adst,
        float* __restrict__ gss, float* __restrict__ gsd,
        const float* __restrict__ ls, const float* __restrict__ lb, int Nt, int Kt) {
    extern __shared__ char smem[];
    const unsigned sb = smem_u32(smem);
    const int tid = threadIdx.x;
    const int wid = tid >> 5, lane = tid & 31;
    const int wr = wid >> 1, wc = wid & 1;
    const int row0 = blockIdx.y * 128;
    const int col0 = blockIdx.x * 128;

    float acc[2][8][4];
#pragma unroll
    for (int mt = 0; mt < 2; mt++)
#pragma unroll
        for (int nt = 0; nt < 8; nt++)
#pragma unroll
            for (int e = 0; e < 4; e++) acc[mt][nt][e] = 0.f;

    const int ltile = lane >> 3, lrow = lane & 7;
    const int nch = Kt >> 6;

    // loader indices: i in [0, 1024), thread does 4; r = row/n, q = 16B group
    const int r_ld = tid >> 3 << 2;   // base handled via loop below
    (void)r_ld;

#define LOAD_CHUNK(cidx, s) do { \
    unsigned base = sb + (s) * STAGE; \
    _Pragma("unroll") \
    for (int j = 0; j < 4; j++) { \
        int i = tid + j * 256; \
        int rr = i >> 3, qq = i & 7; \
        unsigned off = (unsigned)(rr * TROW + qq * 16); \
        size_t ga = (size_t)(row0 + rr) * Kt + (cidx) * 64 + qq * 8; \
        size_t gb = (size_t)(col0 + rr) * Kt + (cidx) * 64 + qq * 8; \
        cpa16(base + P_AHI + off, Ah + ga); \
        cpa16(base + P_ALO + off, Al + ga); \
        cpa16(base + P_BHI + off, Bh + gb); \
        cpa16(base + P_BLO + off, Bl + gb); \
    } \
} while (0)

    LOAD_CHUNK(0, 0);
    CPA_COMMIT();

    for (int c = 0; c < nch; c++) {
        if (c + 1 < nch) {
            LOAD_CHUNK(c + 1, (c + 1) & 1);
            CPA_COMMIT();
            CPA_WAIT1();
        } else {
            CPA_WAIT0();
        }
        __syncthreads();
        unsigned base = sb + (c & 1) * STAGE;
#pragma unroll
        for (int ks = 0; ks < 4; ks++) {
            unsigned ah[2][4], al[2][4];
#pragma unroll
            for (int mt = 0; mt < 2; mt++) {
                int row = wr * 32 + mt * 16 + lrow + (ltile & 1) * 8;
                int kcol = ks * 16 + (ltile >> 1) * 8;
                unsigned off = (unsigned)(row * TROW + kcol * 2);
                ldmat4(ah[mt][0], ah[mt][1], ah[mt][2], ah[mt][3], base + P_AHI + off);
                ldmat4(al[mt][0], al[mt][1], al[mt][2], al[mt][3], base + P_ALO + off);
            }
#pragma unroll
            for (int g = 0; g < 4; g++) {
                int n = wc * 64 + g * 16 + lrow + (ltile >> 1) * 8;
                int kcol = ks * 16 + (ltile & 1) * 8;
                unsigned off = (unsigned)(n * TROW + kcol * 2);
                unsigned bh[4], bl[4];
                ldmat4(bh[0], bh[1], bh[2], bh[3], base + P_BHI + off);
                ldmat4(bl[0], bl[1], bl[2], bl[3], base + P_BLO + off);
#pragma unroll
                for (int mt = 0; mt < 2; mt++)
#pragma unroll
                    for (int half = 0; half < 2; half++) {
                        float* cc = acc[mt][g * 2 + half];
                        mma16816(cc, ah[mt][0], ah[mt][1], ah[mt][2], ah[mt][3],
                                 bh[half * 2], bh[half * 2 + 1]);
                        mma16816(cc, ah[mt][0], ah[mt][1], ah[mt][2], ah[mt][3],
                                 bl[half * 2], bl[half * 2 + 1]);
                        mma16816(cc, al[mt][0], al[mt][1], al[mt][2], al[mt][3],
                                 bh[half * 2], bh[half * 2 + 1]);
                    }
            }
        }
        __syncthreads();
    }
#undef LOAD_CHUNK

    // stage accumulators to smem (stride 132 floats)
    float* stage = (float*)smem;
#pragma unroll
    for (int mt = 0; mt < 2; mt++)
#pragma unroll
        for (int nt = 0; nt < 8; nt++) {
            int row = wr * 32 + mt * 16 + (lane >> 2);
            int col = wc * 64 + nt * 8 + (lane & 3) * 2;
            float2 v0 = make_float2(acc[mt][nt][0], acc[mt][nt][1]);
            float2 v1 = make_float2(acc[mt][nt][2], acc[mt][nt][3]);
            *(float2*)(stage + (size_t)row * 132 + col) = v0;
            *(float2*)(stage + (size_t)(row + 8) * 132 + col) = v1;
        }
    __syncthreads();

    if (LNORM) {
        // Nt==128, grid.x==1 -> fused bias + residual + LayerNorm (+ planar out)
        const int c = lane * 4;
        float4 bb = *(const float4*)(bias + c);
        float4 sv = *(const float4*)(ls + c);
        float4 bv = *(const float4*)(lb + c);
#pragma unroll 4
        for (int rr = 0; rr < 16; rr++) {
            int r = wid * 16 + rr;
            float4 v = *(float4*)(stage + (size_t)r * 132 + c);
            float4 res = *(const float4*)(Rr + (size_t)(row0 + r) * 128 + c);
            v.x += bb.x + res.x; v.y += bb.y + res.y;
            v.z += bb.z + res.z; v.w += bb.w + res.w;
            float s = v.x + v.y + v.z + v.w;
#pragma unroll
            for (int o = 16; o; o >>= 1) s += __shfl_xor_sync(0xFFFFFFFFu, s, o);
            float mean = s * (1.f / 128.f);
            float dx = v.x - mean, dy = v.y - mean, dz = v.z - mean, dw = v.w - mean;
            float qq = dx * dx + dy * dy + dz * dz + dw * dw;
#pragma unroll
            for (int o = 16; o; o >>= 1) qq += __shfl_xor_sync(0xFFFFFFFFu, qq, o);
            float rstd = rsqrtf(qq * (1.f / 128.f) + 1e-5f);
            float4 ov;
            ov.x = dx * rstd * sv.x + bv.x;
            ov.y = dy * rstd * sv.y + bv.y;
            ov.z = dz * rstd * sv.z + bv.z;
            ov.w = dw * rstd * sv.w + bv.w;
            if (C) *(float4*)(C + (size_t)(row0 + r) * 128 + c) = ov;
            if (Ch) {
                uint2 uh, ul;
                uh.x = pack_hi2(ov.x, ov.y); uh.y = pack_hi2(ov.z, ov.w);
                ul.x = pack_lo2(ov.x, ov.y); ul.y = pack_lo2(ov.z, ov.w);
                *(uint2*)(Ch + (size_t)(row0 + r) * 128 + c) = uh;
                *(uint2*)(Cl + (size_t)(row0 + r) * 128 + c) = ul;
            }
        }
    } else {
        for (int i = tid; i < 128 * 32; i += 256) {
            int r = i >> 5, q = i & 31;
            int c = q * 4;
            float4 v = *(float4*)(stage + (size_t)r * 132 + c);
            if (bias) {
                v.x += bias[col0 + c];
                v.y += bias[col0 + c + 1];
                v.z += bias[col0 + c + 2];
                v.w += bias[col0 + c + 3];
            }
            if (RESID) {
                float4 rr = *(const float4*)(Rr + (size_t)(row0 + r) * Nt + col0 + c);
                v.x += rr.x; v.y += rr.y; v.z += rr.z; v.w += rr.w;
            }
            if (ACT == 1) {
                v.x = fmaxf(v.x, 0.f); v.y = fmaxf(v.y, 0.f);
                v.z = fmaxf(v.z, 0.f); v.w = fmaxf(v.w, 0.f);
            }
            if (C) *(float4*)(C + (size_t)(row0 + r) * Nt + col0 + c) = v;
            if (Ch) {
                uint2 uh, ul;
                uh.x = pack_hi2(v.x, v.y); uh.y = pack_hi2(v.z, v.w);
                ul.x = pack_lo2(v.x, v.y); ul.y = pack_lo2(v.z, v.w);
                *(uint2*)(Ch + (size_t)(row0 + r) * Nt + col0 + c) = uh;
                *(uint2*)(Cl + (size_t)(row0 + r) * Nt + col0 + c) = ul;
            }
        }
    }

    if (SCORES && tid < 128) {
        int r = tid;
        float s1 = 0.f, s2 = 0.f;
        const float* as = asrc + col0;
        const float* ad = adst + col0;
        const float* sp = stage + (size_t)r * 132;
#pragma unroll 8
        for (int c = 0; c < 128; c++) {
            float hv = sp[c];
            s1 += hv * as[c];
            s2 += hv * ad[c];
        }
        gss[(size_t)(row0 + r) * 4 + blockIdx.x] = s1;
        gsd[(size_t)(row0 + r) * 4 + blockIdx.x] = s2;
    }
}

// ---------------- weight pre-split; QKV packed per-layer [384, 128] ----------------
__global__ void split_weights(const float* __restrict__ gatW, const float* __restrict__ Wqkv,
                              const float* __restrict__ Wo, const float* __restrict__ Wff1,
                              const float* __restrict__ Wff2) {
    int idx = blockIdx.x * 256 + threadIdx.x;
    if (idx >= WTOT) return;
    float v;
    if (idx < OFF_QKV) {
        int i = idx >> 16, r = idx & 65535;
        int n = r >> 7, k = r & 127;
        v = gatW[(i << 16) + k * 512 + n];
    } else if (idx < OFF_WO) {
        int r0 = idx - OFF_QKV;
        int l = r0 / 49152;
        int rem = r0 - l * 49152;
        int n = rem >> 7, k = rem & 127;
        int s = n >> 7, nc = n & 127;
        v = Wqkv[((l * 3 + s) << 14) + k * 128 + nc];
    } else if (idx < OFF_FF1) {
        int r0 = idx - OFF_WO;
        int i = r0 >> 14, r = r0 & 16383;
        int n = r >> 7, k = r & 127;
        v = Wo[(i << 14) + k * 128 + n];
    } else if (idx < OFF_FF2) {
        int r0 = idx - OFF_FF1;
        int i = r0 >> 16, r = r0 & 65535;
        int n = r >> 7, k = r & 127;
        v = Wff1[(i << 16) + k * 512 + n];
    } else {
        int r0 = idx - OFF_FF2;
        int i = r0 >> 16, r = r0 & 65535;
        int n = r >> 9, k = r & 511;
        v = Wff2[(i << 16) + k * 128 + n];
    }
    __nv_bfloat16 h = __float2bfloat16(v);
    g_wh[idx] = h;
    g_wl[idx] = __float2bfloat16(v - __bfloat162float(h));
}

// ---------------- mask + self-loop init ----------------
__global__ void mask_init(const unsigned char* __restrict__ ego) {
    int idx = blockIdx.x * 256 + threadIdx.x;
    if (idx >= ROWS) return;
    int t = idx >> 10;
    int mm = idx & 1023;
    int b = mm >> 8;
    int n = mm & 255;
    unsigned char v = ego[(b * Tt + t) * 256 + n] ? 1 : 0;
    g_m[idx] = v;
    g_cnt[idx] = v ? 1 : 0;
    g_nbr[idx * MAXD] = (unsigned short)mm;
}

// ---------------- neighbor-list build ----------------
__global__ void build_nbr(const float* __restrict__ A) {
    int tj = blockIdx.x >> 2;
    int i = ((blockIdx.x & 3) << 8) + threadIdx.x;
    if (!g_m[tj]) return;
    int t = tj >> 10;
    int j = tj & 1023;
    if (i == j) return;
    float a = A[(size_t)tj * 1024 + i];
    int ti = (t << 10) + i;
    if (a != 0.f && g_m[ti]) {
        int pos = atomicAdd(&g_cnt[ti], 1);
        if (pos < MAXD) g_nbr[ti * MAXD + pos] = (unsigned short)j;
    }
}

// ---------------- GAT layer-0: fused projection (FIN=2) + src/dst scores ----------------
__global__ void gat0_fused(const float* __restrict__ x, const float* __restrict__ W,
                           const float* __restrict__ asrc, const float* __restrict__ adst) {
    int row = blockIdx.x;
    int d = threadIdx.x;
    int lane = d & 31, wrp = d >> 5;
    float x0 = x[row * 2], x1 = x[row * 2 + 1];
    __shared__ float red[4][8];
    float s1[4], s2[4];
#pragma unroll
    for (int hh = 0; hh < 4; hh++) {
        int c = hh * 128 + d;
        float v = x0 * W[c] + x1 * W[512 + c];
        g_h[(size_t)row * 512 + c] = v;
        s1[hh] = v * asrc[c];
        s2[hh] = v * adst[c];
    }
#pragma unroll
    for (int hh = 0; hh < 4; hh++) {
#pragma unroll
        for (int o = 16; o; o >>= 1) {
            s1[hh] += __shfl_xor_sync(0xFFFFFFFFu, s1[hh], o);
            s2[hh] += __shfl_xor_sync(0xFFFFFFFFu, s2[hh], o);
        }
    }
    if (lane == 0) {
#pragma unroll
        for (int hh = 0; hh < 4; hh++) {
            red[wrp][hh] = s1[hh];
            red[wrp][4 + hh] = s2[hh];
        }
    }
    __syncthreads();
    if (d < 8) {
        float s = red[0][d] + red[1][d] + red[2][d] + red[3][d];
        if (d < 4) g_ss[row * 4 + d] = s;
        else g_sd[row * 4 + (d - 4)] = s;
    }
}

// ---------------- sparse segment-softmax + aggregation -> planar bf16 ----------------
__global__ void gat_agg(const float* __restrict__ bias,
                        __nv_bfloat16* __restrict__ xh, __nv_bfloat16* __restrict__ xl) {
    int row = blockIdx.x;
    int tid = threadIdx.x;
    if (!g_m[row]) {
        xh[(size_t)row * 128 + tid] = __float2bfloat16(0.f);
        xl[(size_t)row * 128 + tid] = __float2bfloat16(0.f);
        return;
    }
    int t = row >> 10;

    __shared__ unsigned short nb[MAXD];
    __shared__ float w[4][MAXD];

    int cnt = g_cnt[row];
    if (cnt > MAXD) cnt = MAXD;
    if (tid < cnt) nb[tid] = g_nbr[(size_t)row * MAXD + tid];

    if (tid < cnt) {
        int jr = (t << 10) + nb[tid];
#pragma unroll
        for (int hh = 0; hh < 4; hh++) {
            float z = g_sd[row * 4 + hh] + g_ss[jr * 4 + hh];
            w[hh][tid] = (z > 0.f) ? z : 0.2f * z;
        }
    } else {
#pragma unroll
        for (int hh = 0; hh < 4; hh++) w[hh][tid] = -INFINITY;
    }
    __syncthreads();

    {
        int wh = tid >> 5, lane = tid & 31;
        float v0 = w[wh][lane], v1 = w[wh][lane + 32], v2 = w[wh][lane + 64], v3 = w[wh][lane + 96];
        float mx = fmaxf(fmaxf(v0, v1), fmaxf(v2, v3));
#pragma unroll
        for (int o = 16; o; o >>= 1) mx = fmaxf(mx, __shfl_xor_sync(0xFFFFFFFFu, mx, o));
        float e0 = expf(v0 - mx), e1 = expf(v1 - mx), e2 = expf(v2 - mx), e3 = expf(v3 - mx);
        float s = e0 + e1 + e2 + e3;
#pragma unroll
        for (int o = 16; o; o >>= 1) s += __shfl_xor_sync(0xFFFFFFFFu, s, o);
        float inv = 1.f / s;
        w[wh][lane] = e0 * inv;
        w[wh][lane + 32] = e1 * inv;
        w[wh][lane + 64] = e2 * inv;
        w[wh][lane + 96] = e3 * inv;
    }
    __syncthreads();

    float acc0 = 0.f, acc1 = 0.f, acc2 = 0.f, acc3 = 0.f;
    const float* hbase = g_h + (((size_t)(t << 10)) << 9) + tid;
    int j = 0;
    for (; j + 4 <= cnt; j += 4) {
        const float* p0 = hbase + ((size_t)nb[j] << 9);
        const float* p1 = hbase + ((size_t)nb[j + 1] << 9);
        const float* p2 = hbase + ((size_t)nb[j + 2] << 9);
        const float* p3 = hbase + ((size_t)nb[j + 3] << 9);
#pragma unroll
        for (int hh = 0; hh < 4; hh++) {
            acc0 += w[hh][j] * p0[hh << 7];
            acc1 += w[hh][j + 1] * p1[hh << 7];
            acc2 += w[hh][j + 2] * p2[hh << 7];
            acc3 += w[hh][j + 3] * p3[hh << 7];
        }
    }
    for (; j < cnt; j++) {
        const float* p0 = hbase + ((size_t)nb[j] << 9);
#pragma unroll
        for (int hh = 0; hh < 4; hh++) acc0 += w[hh][j] * p0[hh << 7];
    }
    float o = (acc0 + acc1 + acc2 + acc3) * 0.25f + bias[tid];
    o = fmaxf(o, 0.f);
    __nv_bfloat16 hi = __float2bfloat16(o);
    xh[(size_t)row * 128 + tid] = hi;
    xl[(size_t)row * 128 + tid] = __float2bfloat16(o - __bfloat162float(hi));
}

// ---------------- transpose to sequence layout + PE (planar in, fp32 + planar out) ----------------
__global__ void to_seq(const __nv_bfloat16* __restrict__ xh, const __nv_bfloat16* __restrict__ xl) {
    int idx = blockIdx.x * 256 + threadIdx.x;
    int row = idx >> 7;
    int d = idx & 127;
    int t = row >> 10;
    int mm = row & 1023;
    float x = __bfloat162float(xh[idx]) + __bfloat162float(xl[idx]);
    float freq = expf(-(float)(d & ~1) * (9.210340371976184f / 128.f));
    float ang = (float)t * freq;
    float pe = (d & 1) ? cosf(ang) : sinf(ang);
    float v = x + pe;
    size_t sidx = ((size_t)mm * Tt + t) * Hh + d;
    g_xs[sidx] = v;
    __nv_bfloat16 hi = __float2bfloat16(v);
    g_xsh[sidx] = hi;
    g_xsl[sidx] = __float2bfloat16(v - __bfloat162float(hi));
}

// ---------------- per-sequence attention (T=16, 4 heads of 32), packed QKV -> planar out ----------------
__global__ void attn_kernel(const float* __restrict__ QKV,
                            __nv_bfloat16* __restrict__ Oh, __nv_bfloat16* __restrict__ Ol) {
    __shared__ float sq[16][128], sk[16][128], sv[16][128];
    int m = blockIdx.x;
    int tid = threadIdx.x;
    size_t base = (size_t)m * 16 * 384;
    for (int idx = tid; idx < 2048; idx += 128) {
        int t = idx >> 7, d = idx & 127;
        size_t p = base + (size_t)t * 384 + d;
        sq[t][d] = QKV[p];
        sk[t][d] = QKV[p + 128];
        sv[t][d] = QKV[p + 256];
    }
    __syncthreads();
    int h = tid >> 5;
    int tq = (tid >> 1) & 15;
    int half = tid & 1;
    const float scale = 0.17677669529663687f;
    float sc[16];
    float mx = -1e30f;
#pragma unroll
    for (int tk = 0; tk < 16; tk++) {
        float s = 0.f;
#pragma unroll
        for (int dd = 0; dd < 16; dd++) {
            int d = half * 16 + dd;
            s += sq[tq][h * 32 + d] * sk[tk][h * 32 + d];
        }
        s += __shfl_xor_sync(0xFFFFFFFFu, s, 1);
        s *= scale;
        sc[tk] = s;
        mx = fmaxf(mx, s);
    }
    float sum = 0.f;
#pragma unroll
    for (int tk = 0; tk < 16; tk++) { sc[tk] = expf(sc[tk] - mx); sum += sc[tk]; }
    float inv = 1.f / sum;
    size_t ob = (size_t)m * 16 * 128 + (size_t)tq * 128 + h * 32 + half * 16;
#pragma unroll
    for (int dd = 0; dd < 16; dd++) {
        int d = half * 16 + dd;
        float o = 0.f;
#pragma unroll
        for (int tk = 0; tk < 16; tk++) o += sc[tk] * sv[tk][h * 32 + d];
        o *= inv;
        __nv_bfloat16 hi = __float2bfloat16(o);
        Oh[ob + dd] = hi;
        Ol[ob + dd] = __float2bfloat16(o - __bfloat162float(hi));
    }
}

// ---------------- launcher ----------------
extern "C" void kernel_launch(void* const* d_in, const int* in_sizes, int n_in,
                              void* d_out, int out_size) {
    const unsigned char* ego = (const unsigned char*)d_in[0];
    const float* positions  = (const float*)d_in[1];
    const float* adjacency  = (const float*)d_in[2];
    const float* gat1_W     = (const float*)d_in[3];
    const float* gat1_asrc  = (const float*)d_in[4];
    const float* gat1_adst  = (const float*)d_in[5];
    const float* gat1_b     = (const float*)d_in[6];
    const float* gatW       = (const float*)d_in[7];
    const float* gat_asrc   = (const float*)d_in[8];
    const float* gat_adst   = (const float*)d_in[9];
    const float* gat_b      = (const float*)d_in[10];
    const float* Wqkv       = (const float*)d_in[11];
    const float* bqkv       = (const float*)d_in[12];
    const float* Wo         = (const float*)d_in[13];
    const float* bo         = (const float*)d_in[14];
    const float* ln1_s      = (const float*)d_in[15];
    const float* ln1_b      = (const float*)d_in[16];
    const float* ln2_s      = (const float*)d_in[17];
    const float* ln2_b      = (const float*)d_in[18];
    const float* Wff1       = (const float*)d_in[19];
    const float* bff1       = (const float*)d_in[20];
    const float* Wff2       = (const float*)d_in[21];
    const float* bff2       = (const float*)d_in[22];
    float* out = (float*)d_out;

    float *h, *xs, *ss, *sd;
    __nv_bfloat16 *wh, *wl, *xah, *xal, *xbh, *xbl, *xsh, *xsl, *atth, *attl, *ffh, *ffl;
    cudaGetSymbolAddress((void**)&h,    g_h);
    cudaGetSymbolAddress((void**)&xs,   g_xs);
    cudaGetSymbolAddress((void**)&ss,   g_ss);
    cudaGetSymbolAddress((void**)&sd,   g_sd);
    cudaGetSymbolAddress((void**)&wh,   g_wh);
    cudaGetSymbolAddress((void**)&wl,   g_wl);
    cudaGetSymbolAddress((void**)&xah,  g_xah);
    cudaGetSymbolAddress((void**)&xal,  g_xal);
    cudaGetSymbolAddress((void**)&xbh,  g_xbh);
    cudaGetSymbolAddress((void**)&xbl,  g_xbl);
    cudaGetSymbolAddress((void**)&xsh,  g_xsh);
    cudaGetSymbolAddress((void**)&xsl,  g_xsl);
    cudaGetSymbolAddress((void**)&atth, g_atth);
    cudaGetSymbolAddress((void**)&attl, g_attl);
    cudaGetSymbolAddress((void**)&ffh,  g_ffh);
    cudaGetSymbolAddress((void**)&ffl,  g_ffl);

    cudaFuncSetAttribute(gemm_tc<0, false, true,  false>, cudaFuncAttributeMaxDynamicSharedMemorySize, GSM_TOTAL);
    cudaFuncSetAttribute(gemm_tc<0, false, false, false>, cudaFuncAttributeMaxDynamicSharedMemorySize, GSM_TOTAL);
    cudaFuncSetAttribute(gemm_tc<0, true,  false, true >, cudaFuncAttributeMaxDynamicSharedMemorySize, GSM_TOTAL);
    cudaFuncSetAttribute(gemm_tc<1, false, false, false>, cudaFuncAttributeMaxDynamicSharedMemorySize, GSM_TOTAL);

    split_weights<<<(WTOT + 255) / 256, 256>>>(gatW, Wqkv, Wo, Wff1, Wff2);
    mask_init<<<ROWS / 256, 256>>>(ego);
    build_nbr<<<ROWS * 4, 256>>>(adjacency);

    // GAT layer 0 (FIN=2)
    gat0_fused<<<ROWS, 128>>>(positions, gat1_W, gat1_asrc, gat1_adst);
    gat_agg<<<ROWS, 128>>>(gat1_b, xah, xal);

    // GAT layers 1..5
    __nv_bfloat16 *curh = xah, *curl = xal, *nxth = xbh, *nxtl = xbl;
    for (int i = 0; i < 5; i++) {
        dim3 gp(4, ROWS / 128);
        gemm_tc<0, false, true, false><<<gp, 256, GSM_TOTAL>>>(
            curh, curl, wh + OFF_GAT + (size_t)i * 65536, wl + OFF_GAT + (size_t)i * 65536,
            nullptr, nullptr, h, nullptr, nullptr,
            gat_asrc + i * 512, gat_adst + i * 512, ss, sd, nullptr, nullptr, 512, 128);
        gat_agg<<<ROWS, 128>>>(gat_b + i * 128, nxth, nxtl);
        __nv_bfloat16* t0 = curh; curh = nxth; nxth = t0;
        __nv_bfloat16* t1 = curl; curl = nxtl; nxtl = t1;
    }

    to_seq<<<ROWS * 128 / 256, 256>>>(curh, curl);

    dim3 g1(1, ROWS / 128);
    dim3 g2(4, ROWS / 128);
    dim3 gq(3, ROWS / 128);
    for (int l = 0; l < NL_TR; l++) {
        // fused QKV GEMM -> g_h [ROWS][384] fp32
        size_t oq = OFF_QKV + (size_t)l * 49152;
        gemm_tc<0, false, false, false><<<gq, 256, GSM_TOTAL>>>(
            xsh, xsl, wh + oq, wl + oq,
            bqkv + l * 384, nullptr, h, nullptr, nullptr,
            nullptr, nullptr, nullptr, nullptr, nullptr, nullptr, 384, 128);
        attn_kernel<<<Mm, 128>>>(h, atth, attl);
        // Wo GEMM + bias + residual + LN1 -> xs fp32 + planar
        size_t owo = OFF_WO + (size_t)l * 16384;
        gemm_tc<0, true, false, true><<<g1, 256, GSM_TOTAL>>>(
            atth, attl, wh + owo, wl + owo,
            bo + l * 128, xs, xs, xsh, xsl,
            nullptr, nullptr, nullptr, nullptr,
            ln1_s + l * 128, ln1_b + l * 128, 128, 128);
        // FF1 GEMM + ReLU -> planar only
        size_t of1 = OFF_FF1 + (size_t)l * 65536;
        gemm_tc<1, false, false, false><<<g2, 256, GSM_TOTAL>>>(
            xsh, xsl, wh + of1, wl + of1,
            bff1 + l * 512, nullptr, nullptr, ffh, ffl,
            nullptr, nullptr, nullptr, nullptr, nullptr, nullptr, 512, 128);
        // FF2 GEMM + bias + residual + LN2
        size_t of2 = OFF_FF2 + (size_t)l * 65536;
        if (l == NL_TR - 1) {
            gemm_tc<0, true, false, true><<<g1, 256, GSM_TOTAL>>>(
                ffh, ffl, wh + of2, wl + of2,
                bff2 + l * 128, xs, out, nullptr, nullptr,
                nullptr, nullptr, nullptr, nullptr,
                ln2_s + l * 128, ln2_b + l * 128, 128, 512);
        } else {
            gemm_tc<0, true, false, true><<<g1, 256, GSM_TOTAL>>>(
                ffh, ffl, wh + of2, wl + of2,
                bff2 + l * 128, xs, xs, xsh, xsl,
                nullptr, nullptr, nullptr, nullptr,
                ln2_s + l * 128, ln2_b + l * 128, 128, 512);
        }
    }
}